// round 1
// baseline (speedup 1.0000x reference)
#include <cuda_runtime.h>
#include <math.h>

#define NN_NODE 10000
#define E_NUM   320000
#define FDIM    256
#define NLAYERS 5
#define OC      128
#define KTOT    (NLAYERS*FDIM)   // 1280

// ---------------- scratch (no allocation allowed) ----------------
__device__ float g_dinv[2][NN_NODE];          // deg accumulator, then 1/sqrt(deg)
__device__ int   g_cnt[2][NN_NODE];
__device__ int   g_rowptr[2][NN_NODE + 1];
__device__ int   g_csr_src[2][E_NUM];
__device__ float g_csr_norm[2][E_NUM];
__device__ float g_feats[2][(size_t)NN_NODE * KTOT];   // packed [n][layer*256+f]
__device__ float g_h1[(size_t)NN_NODE * FDIM];
__device__ float g_amax[2][NLAYERS];
__device__ float g_atts[2][NLAYERS];
__device__ float g_weff[2][OC * KTOT];
__device__ float g_emb[2][(size_t)NN_NODE * OC];

// ---------------- small prep kernels ----------------
__global__ void k_init() {
    int i = blockIdx.x * blockDim.x + threadIdx.x;
    if (i < NN_NODE) {
        g_dinv[0][i] = 1.0f; g_dinv[1][i] = 1.0f;  // self-loop weight
        g_cnt[0][i] = 0;     g_cnt[1][i] = 0;
    }
    if (i < NLAYERS) { g_amax[0][i] = 0.0f; g_amax[1][i] = 0.0f; }
}

__global__ void k_deg_cnt(const int* __restrict__ edges, const float* __restrict__ w, int b) {
    int e = blockIdx.x * blockDim.x + threadIdx.x;
    if (e < E_NUM) {
        int dst = edges[E_NUM + e];
        atomicAdd(&g_dinv[b][dst], w[e]);
        atomicAdd(&g_cnt[b][dst], 1);
    }
}

__global__ void k_rsqrt(int b) {
    int i = blockIdx.x * blockDim.x + threadIdx.x;
    if (i < NN_NODE) g_dinv[b][i] = rsqrtf(g_dinv[b][i]);   // deg >= 1 always
}

__global__ void k_scan(int b) {
    __shared__ int part[1024];
    const int PER = 10;                           // 1024*10 >= 10000
    int tid = threadIdx.x;
    int base = tid * PER;
    int local[PER];
    int s = 0;
    for (int j = 0; j < PER; j++) {
        int idx = base + j;
        int v = (idx < NN_NODE) ? g_cnt[b][idx] : 0;
        local[j] = v; s += v;
    }
    part[tid] = s;
    __syncthreads();
    for (int off = 1; off < 1024; off <<= 1) {
        int v = (tid >= off) ? part[tid - off] : 0;
        __syncthreads();
        part[tid] += v;
        __syncthreads();
    }
    int run = tid ? part[tid - 1] : 0;
    for (int j = 0; j < PER; j++) {
        int idx = base + j;
        if (idx < NN_NODE) {
            g_rowptr[b][idx] = run;
            run += local[j];
            g_cnt[b][idx] = 0;                    // reset as cursor for fill
        }
    }
    if (tid == 1023) g_rowptr[b][NN_NODE] = part[1023];
}

__global__ void k_fill(const int* __restrict__ edges, const float* __restrict__ w, int b) {
    int e = blockIdx.x * blockDim.x + threadIdx.x;
    if (e < E_NUM) {
        int s = edges[e];
        int d = edges[E_NUM + e];
        int pos = g_rowptr[b][d] + atomicAdd(&g_cnt[b][d], 1);
        g_csr_src[b][pos] = s;
        g_csr_norm[b][pos] = g_dinv[b][s] * w[e] * g_dinv[b][d];
    }
}

// ---------------- aggregation:  feats[v, L*256+f] = relu(selfnorm*h1[v] + sum norm*h1[src] + bias) ----------------
__global__ void k_aggregate(const float* __restrict__ h1, int b,
                            const float* __restrict__ bias, int layer) {
    int v = blockIdx.x;
    int f = threadIdx.x;
    float dv = g_dinv[b][v];
    float acc = dv * dv * h1[(size_t)v * FDIM + f];
    int e = g_rowptr[b][v];
    int e2 = g_rowptr[b][v + 1];
    const int*   srcs  = g_csr_src[b];
    const float* norms = g_csr_norm[b];
    for (; e + 4 <= e2; e += 4) {
        int u0 = srcs[e], u1 = srcs[e + 1], u2 = srcs[e + 2], u3 = srcs[e + 3];
        float n0 = norms[e], n1 = norms[e + 1], n2 = norms[e + 2], n3 = norms[e + 3];
        float a0 = h1[(size_t)u0 * FDIM + f];
        float a1 = h1[(size_t)u1 * FDIM + f];
        float a2 = h1[(size_t)u2 * FDIM + f];
        float a3 = h1[(size_t)u3 * FDIM + f];
        acc += n0 * a0 + n1 * a1 + n2 * a2 + n3 * a3;
    }
    for (; e < e2; e++) acc += norms[e] * h1[(size_t)srcs[e] * FDIM + f];
    acc += bias[f];
    g_feats[b][(size_t)v * KTOT + layer * FDIM + f] = fmaxf(acc, 0.0f);
}

// ---------------- generic 128x128x8 fp32 GEMM  (C = A @ B or A @ B^T) ----------------
// A: [M,K] row-major lda.  TRANSB=0: B [K,N] ldb (N multiple of 128 required).
// TRANSB=1: B [N,K] row-major ldb.  K multiple of 8 required.
template <int TRANSB, int BIAS>
__global__ __launch_bounds__(256) void k_gemm(int M, int N, int K,
        const float* __restrict__ A, int lda,
        const float* __restrict__ B, int ldb,
        float* __restrict__ C, int ldc,
        const float* __restrict__ bias) {
    __shared__ float As[8][128];
    __shared__ float Bs[8][128];
    int tid = threadIdx.x;
    int tx = tid & 15, ty = tid >> 4;
    int i0 = blockIdx.y * 128, j0 = blockIdx.x * 128;
    int ar = tid >> 1, ak = (tid & 1) * 4;

    float acc[8][8];
    #pragma unroll
    for (int r = 0; r < 8; r++)
        #pragma unroll
        for (int c = 0; c < 8; c++) acc[r][c] = 0.0f;

    for (int k0 = 0; k0 < K; k0 += 8) {
        float4 av = make_float4(0.f, 0.f, 0.f, 0.f);
        if (i0 + ar < M) av = *(const float4*)(A + (size_t)(i0 + ar) * lda + k0 + ak);
        As[ak + 0][ar] = av.x; As[ak + 1][ar] = av.y;
        As[ak + 2][ar] = av.z; As[ak + 3][ar] = av.w;
        if (TRANSB) {
            float4 bv = make_float4(0.f, 0.f, 0.f, 0.f);
            if (j0 + ar < N) bv = *(const float4*)(B + (size_t)(j0 + ar) * ldb + k0 + ak);
            Bs[ak + 0][ar] = bv.x; Bs[ak + 1][ar] = bv.y;
            Bs[ak + 2][ar] = bv.z; Bs[ak + 3][ar] = bv.w;
        } else {
            int bk = tid >> 5, bn = (tid & 31) * 4;
            float4 bv = *(const float4*)(B + (size_t)(k0 + bk) * ldb + j0 + bn);
            *(float4*)&Bs[bk][bn] = bv;
        }
        __syncthreads();
        #pragma unroll
        for (int k = 0; k < 8; k++) {
            float a[8], bb[8];
            *(float4*)&a[0]  = *(const float4*)&As[k][ty * 8];
            *(float4*)&a[4]  = *(const float4*)&As[k][ty * 8 + 4];
            *(float4*)&bb[0] = *(const float4*)&Bs[k][tx * 8];
            *(float4*)&bb[4] = *(const float4*)&Bs[k][tx * 8 + 4];
            #pragma unroll
            for (int r = 0; r < 8; r++)
                #pragma unroll
                for (int c = 0; c < 8; c++) acc[r][c] += a[r] * bb[c];
        }
        __syncthreads();
    }
    #pragma unroll
    for (int r = 0; r < 8; r++) {
        int i = i0 + ty * 8 + r;
        if (i >= M) continue;
        #pragma unroll
        for (int c = 0; c < 8; c++) {
            int j = j0 + tx * 8 + c;
            if (j < N) {
                float v = acc[r][c];
                if (BIAS) v += bias[j];
                C[(size_t)i * ldc + j] = v;
            }
        }
    }
}

// ---------------- channel attention ----------------
__global__ void k_attmax(int b) {
    __shared__ float red[256];
    float m[NLAYERS] = {0.f, 0.f, 0.f, 0.f, 0.f};
    const float* f = g_feats[b];
    for (int r = blockIdx.x; r < NN_NODE; r += gridDim.x) {
        #pragma unroll
        for (int c = 0; c < NLAYERS; c++)
            m[c] = fmaxf(m[c], f[(size_t)r * KTOT + c * FDIM + threadIdx.x]);
    }
    for (int c = 0; c < NLAYERS; c++) {
        red[threadIdx.x] = m[c];
        __syncthreads();
        for (int o = 128; o > 0; o >>= 1) {
            if (threadIdx.x < o) red[threadIdx.x] = fmaxf(red[threadIdx.x], red[threadIdx.x + o]);
            __syncthreads();
        }
        if (threadIdx.x == 0)
            atomicMax((int*)&g_amax[b][c], __float_as_int(red[0]));   // values >= 0
        __syncthreads();
    }
}

__global__ void k_attfc(const float* __restrict__ fc1w, const float* __restrict__ fc1b,
                        const float* __restrict__ fc2w, const float* __restrict__ fc2b, int b) {
    if (threadIdx.x == 0 && blockIdx.x == 0) {
        float a[NLAYERS];
        for (int c = 0; c < NLAYERS; c++) a[c] = g_amax[b][c];
        float t[5 * NLAYERS];
        for (int j = 0; j < 5 * NLAYERS; j++) {
            float s = fc1b[j];
            for (int c = 0; c < NLAYERS; c++) s += fc1w[j * NLAYERS + c] * a[c];
            t[j] = fmaxf(s, 0.f);
        }
        for (int c = 0; c < NLAYERS; c++) {
            float s = fc2b[c];
            for (int j = 0; j < 5 * NLAYERS; j++) s += fc2w[c * (5 * NLAYERS) + j] * t[j];
            g_atts[b][c] = 1.0f / (1.0f + expf(-s));
        }
    }
}

__global__ void k_weff(const float* __restrict__ cw, int b) {
    int idx = blockIdx.x * blockDim.x + threadIdx.x;
    if (idx < OC * KTOT) {
        int c = (idx % KTOT) >> 8;   // layer channel
        g_weff[b][idx] = cw[idx] * g_atts[b][c];
    }
}

// ---------------- launch ----------------
extern "C" void kernel_launch(void* const* d_in, const int* in_sizes, int n_in,
                              void* d_out, int out_size) {
    const float* x_m    = (const float*)d_in[0];
    const float* x_d    = (const float*)d_in[1];
    const float* w_m    = (const float*)d_in[2];
    const float* w_d    = (const float*)d_in[3];
    const float* Wx     = (const float*)d_in[4];
    const float* bx     = (const float*)d_in[5];
    const float* Wy     = (const float*)d_in[6];
    const float* by     = (const float*)d_in[7];
    const float* fc1x_w = (const float*)d_in[8];
    const float* fc1x_b = (const float*)d_in[9];
    const float* fc2x_w = (const float*)d_in[10];
    const float* fc2x_b = (const float*)d_in[11];
    const float* fc1y_w = (const float*)d_in[12];
    const float* fc1y_b = (const float*)d_in[13];
    const float* fc2y_w = (const float*)d_in[14];
    const float* fc2y_b = (const float*)d_in[15];
    const float* cnnx_w = (const float*)d_in[16];
    const float* cnnx_b = (const float*)d_in[17];
    const float* cnny_w = (const float*)d_in[18];
    const float* cnny_b = (const float*)d_in[19];
    const int*   edges_m = (const int*)d_in[20];
    const int*   edges_d = (const int*)d_in[21];
    float* out = (float*)d_out;

    // resolve scratch symbol addresses (no allocation)
    float *p_h1, *p_feats, *p_weff, *p_emb;
    cudaGetSymbolAddress((void**)&p_h1,    g_h1);
    cudaGetSymbolAddress((void**)&p_feats, g_feats);
    cudaGetSymbolAddress((void**)&p_weff,  g_weff);
    cudaGetSymbolAddress((void**)&p_emb,   g_emb);

    const int MT = (NN_NODE + 127) / 128;   // 79

    k_init<<<(NN_NODE + 255) / 256, 256>>>();

    for (int b = 0; b < 2; b++) {
        const int*   edges = b ? edges_d : edges_m;
        const float* w     = b ? w_d : w_m;
        const float* W     = b ? Wy : Wx;
        const float* bias  = b ? by : bx;
        const float* fc1w  = b ? fc1y_w : fc1x_w;
        const float* fc1b  = b ? fc1y_b : fc1x_b;
        const float* fc2w  = b ? fc2y_w : fc2x_w;
        const float* fc2b  = b ? fc2y_b : fc2x_b;
        const float* cw    = b ? cnny_w : cnnx_w;
        const float* cb    = b ? cnny_b : cnnx_b;
        float* featsB = p_feats + (size_t)b * NN_NODE * KTOT;

        k_deg_cnt<<<E_NUM / 256, 256>>>(edges, w, b);
        k_rsqrt<<<(NN_NODE + 255) / 256, 256>>>(b);
        k_scan<<<1, 1024>>>(b);
        k_fill<<<E_NUM / 256, 256>>>(edges, w, b);

        const float* hin = b ? x_d : x_m;
        int lda = FDIM;
        for (int i = 0; i < NLAYERS; i++) {
            k_gemm<0, 0><<<dim3(FDIM / 128, MT), 256>>>(
                NN_NODE, FDIM, FDIM, hin, lda, W + (size_t)i * FDIM * FDIM, FDIM,
                p_h1, FDIM, nullptr);
            k_aggregate<<<NN_NODE, 256>>>(p_h1, b, bias + (size_t)i * FDIM, i);
            hin = featsB + (size_t)i * FDIM;
            lda = KTOT;
        }

        k_attmax<<<256, 256>>>(b);
        k_attfc<<<1, 32>>>(fc1w, fc1b, fc2w, fc2b, b);
        k_weff<<<(OC * KTOT + 255) / 256, 256>>>(cw, b);

        k_gemm<1, 1><<<dim3(1, MT), 256>>>(
            NN_NODE, OC, KTOT, featsB, KTOT,
            p_weff + (size_t)b * OC * KTOT, KTOT,
            p_emb + (size_t)b * NN_NODE * OC, OC, cb);
    }

    // final: out[i,j] = embX[i,:] . embY[j,:]
    k_gemm<1, 0><<<dim3(MT, MT), 256>>>(
        NN_NODE, NN_NODE, OC,
        p_emb, OC,
        p_emb + (size_t)NN_NODE * OC, OC,
        out, NN_NODE, nullptr);
}

// round 2
// speedup vs baseline: 2.1178x; 2.1178x over previous
#include <cuda_runtime.h>
#include <math.h>
#include <stdint.h>

#define NN_NODE 10000
#define E_NUM   320000
#define FDIM    256
#define NLAYERS 5
#define OC      128
#define KTOT    (NLAYERS*FDIM)   // 1280

// ---------------- scratch (no allocation allowed) ----------------
__device__ float g_dinv[2][NN_NODE];
__device__ int   g_cnt[2][NN_NODE];
__device__ int   g_rowptr[2][NN_NODE + 1];
__device__ int   g_csr_src[2][E_NUM];
__device__ float g_csr_norm[2][E_NUM];
__device__ __align__(16) float g_feats[2][(size_t)NN_NODE * KTOT];
__device__ __align__(16) float g_h1[(size_t)NN_NODE * FDIM];
__device__ float g_amax[2][NLAYERS];
__device__ float g_atts[2][NLAYERS];
__device__ __align__(16) float g_weff[2][OC * KTOT];
__device__ __align__(16) float g_emb[2][(size_t)NN_NODE * OC];

// ---------------- small prep kernels ----------------
__global__ void k_init() {
    int i = blockIdx.x * blockDim.x + threadIdx.x;
    if (i < NN_NODE) {
        g_dinv[0][i] = 1.0f; g_dinv[1][i] = 1.0f;
        g_cnt[0][i] = 0;     g_cnt[1][i] = 0;
    }
    if (i < NLAYERS) { g_amax[0][i] = 0.0f; g_amax[1][i] = 0.0f; }
}

__global__ void k_deg_cnt(const int* __restrict__ edges, const float* __restrict__ w, int b) {
    int e = blockIdx.x * blockDim.x + threadIdx.x;
    if (e < E_NUM) {
        int dst = edges[E_NUM + e];
        atomicAdd(&g_dinv[b][dst], w[e]);
        atomicAdd(&g_cnt[b][dst], 1);
    }
}

__global__ void k_rsqrt(int b) {
    int i = blockIdx.x * blockDim.x + threadIdx.x;
    if (i < NN_NODE) g_dinv[b][i] = rsqrtf(g_dinv[b][i]);
}

__global__ void k_scan(int b) {
    __shared__ int wsum[32];
    const int PER = 10;
    int tid = threadIdx.x, lane = tid & 31, w = tid >> 5;
    int local[PER]; int s = 0;
    #pragma unroll
    for (int j = 0; j < PER; j++) {
        int idx = tid * PER + j;
        int v = (idx < NN_NODE) ? g_cnt[b][idx] : 0;
        local[j] = v; s += v;
    }
    int sc = s;
    #pragma unroll
    for (int off = 1; off < 32; off <<= 1) {
        int u = __shfl_up_sync(0xffffffffu, sc, off);
        if (lane >= off) sc += u;
    }
    if (lane == 31) wsum[w] = sc;
    __syncthreads();
    if (w == 0) {
        int v = wsum[lane]; int vs = v;
        #pragma unroll
        for (int off = 1; off < 32; off <<= 1) {
            int u = __shfl_up_sync(0xffffffffu, vs, off);
            if (lane >= off) vs += u;
        }
        wsum[lane] = vs;
    }
    __syncthreads();
    int base = (w ? wsum[w - 1] : 0) + sc - s;
    #pragma unroll
    for (int j = 0; j < PER; j++) {
        int idx = tid * PER + j;
        if (idx < NN_NODE) {
            g_rowptr[b][idx] = base;
            base += local[j];
            g_cnt[b][idx] = 0;
        }
    }
    if (tid == 1023) g_rowptr[b][NN_NODE] = wsum[31];
}

__global__ void k_fill(const int* __restrict__ edges, const float* __restrict__ w, int b) {
    int e = blockIdx.x * blockDim.x + threadIdx.x;
    if (e < E_NUM) {
        int s = edges[e];
        int d = edges[E_NUM + e];
        int pos = g_rowptr[b][d] + atomicAdd(&g_cnt[b][d], 1);
        g_csr_src[b][pos] = s;
        g_csr_norm[b][pos] = g_dinv[b][s] * w[e] * g_dinv[b][d];
    }
}

// ---------------- aggregation ----------------
__global__ void k_aggregate(const float* __restrict__ h1, int b,
                            const float* __restrict__ bias, int layer) {
    int v = blockIdx.x;
    int f = threadIdx.x;
    float dv = g_dinv[b][v];
    float acc = dv * dv * h1[(size_t)v * FDIM + f];
    int e = g_rowptr[b][v];
    int e2 = g_rowptr[b][v + 1];
    const int*   srcs  = g_csr_src[b];
    const float* norms = g_csr_norm[b];
    for (; e + 4 <= e2; e += 4) {
        int u0 = srcs[e], u1 = srcs[e + 1], u2 = srcs[e + 2], u3 = srcs[e + 3];
        float n0 = norms[e], n1 = norms[e + 1], n2 = norms[e + 2], n3 = norms[e + 3];
        float a0 = h1[(size_t)u0 * FDIM + f];
        float a1 = h1[(size_t)u1 * FDIM + f];
        float a2 = h1[(size_t)u2 * FDIM + f];
        float a3 = h1[(size_t)u3 * FDIM + f];
        acc += n0 * a0 + n1 * a1 + n2 * a2 + n3 * a3;
    }
    for (; e < e2; e++) acc += norms[e] * h1[(size_t)srcs[e] * FDIM + f];
    acc += bias[f];
    g_feats[b][(size_t)v * KTOT + layer * FDIM + f] = fmaxf(acc, 0.0f);
}

// ---------------- TF32 tensor-core GEMM 128x128x16 ----------------
__device__ __forceinline__ uint32_t f2tf(float x) {
    uint32_t u; asm("cvt.rna.tf32.f32 %0, %1;" : "=r"(u) : "f"(x)); return u;
}

#define MMA_TF32(d, a, b) \
  asm volatile("mma.sync.aligned.m16n8k8.row.col.f32.tf32.tf32.f32 " \
      "{%0,%1,%2,%3}, {%4,%5,%6,%7}, {%8,%9}, {%0,%1,%2,%3};" \
      : "+f"(d[0]), "+f"(d[1]), "+f"(d[2]), "+f"(d[3]) \
      : "r"(a[0]), "r"(a[1]), "r"(a[2]), "r"(a[3]), "r"(b[0]), "r"(b[1]))

// A [M,K] row-major. TRANSB=0: B [K,N] (N multiple of 128). TRANSB=1: B [N,K].
// K multiple of 16.
template <int TRANSB, int BIAS>
__global__ __launch_bounds__(256) void k_gemm_tf32(
        int M, int N, int K,
        const float* __restrict__ A, int lda,
        const float* __restrict__ B, int ldb,
        float* __restrict__ C, int ldc,
        const float* __restrict__ bias) {
    constexpr int LDA_S = 20;            // 16 + 4 pad  (bank-conflict-free frags)
    constexpr int LDB0  = 136;           // Bs[k][n] for TRANSB=0
    constexpr int LDB1  = 20;            // Bs[n][k] for TRANSB=1
    __shared__ uint32_t As[2][128 * LDA_S];
    __shared__ uint32_t Bs[2][TRANSB ? 128 * LDB1 : 16 * LDB0];

    const int tid = threadIdx.x;
    const int wid = tid >> 5;
    const int lane = tid & 31;
    const int g = lane >> 2, t = lane & 3;
    const int wm = wid >> 1, wn = wid & 1;       // warp tile: 32 rows x 64 cols
    const int i0 = blockIdx.y * 128, j0 = blockIdx.x * 128;

    const int ar  = tid >> 1, akc = (tid & 1) * 8;     // A/Bt loads: 128 rows x 16k
    const int bkr = tid >> 4, bnc = (tid & 15) * 8;    // B (no-trans): 16k x 128n

    float acc[2][8][4];
    #pragma unroll
    for (int mt = 0; mt < 2; mt++)
        #pragma unroll
        for (int nt = 0; nt < 8; nt++)
            #pragma unroll
            for (int q = 0; q < 4; q++) acc[mt][nt][q] = 0.0f;

    float4 a0v, a1v, b0v, b1v;
    const float4 z4 = make_float4(0.f, 0.f, 0.f, 0.f);

    auto g_load = [&](int k0) {
        a0v = z4; a1v = z4;
        if (i0 + ar < M) {
            const float* p = A + (size_t)(i0 + ar) * lda + k0 + akc;
            a0v = *(const float4*)p;
            a1v = *(const float4*)(p + 4);
        }
        if (TRANSB) {
            b0v = z4; b1v = z4;
            if (j0 + ar < N) {
                const float* p = B + (size_t)(j0 + ar) * ldb + k0 + akc;
                b0v = *(const float4*)p;
                b1v = *(const float4*)(p + 4);
            }
        } else {
            const float* p = B + (size_t)(k0 + bkr) * ldb + j0 + bnc;
            b0v = *(const float4*)p;
            b1v = *(const float4*)(p + 4);
        }
    };

    auto s_store = [&](int buf) {
        uint4 u0 = make_uint4(f2tf(a0v.x), f2tf(a0v.y), f2tf(a0v.z), f2tf(a0v.w));
        uint4 u1 = make_uint4(f2tf(a1v.x), f2tf(a1v.y), f2tf(a1v.z), f2tf(a1v.w));
        *(uint4*)&As[buf][ar * LDA_S + akc]     = u0;
        *(uint4*)&As[buf][ar * LDA_S + akc + 4] = u1;
        uint4 v0 = make_uint4(f2tf(b0v.x), f2tf(b0v.y), f2tf(b0v.z), f2tf(b0v.w));
        uint4 v1 = make_uint4(f2tf(b1v.x), f2tf(b1v.y), f2tf(b1v.z), f2tf(b1v.w));
        if (TRANSB) {
            *(uint4*)&Bs[buf][ar * LDB1 + akc]     = v0;
            *(uint4*)&Bs[buf][ar * LDB1 + akc + 4] = v1;
        } else {
            *(uint4*)&Bs[buf][bkr * LDB0 + bnc]     = v0;
            *(uint4*)&Bs[buf][bkr * LDB0 + bnc + 4] = v1;
        }
    };

    auto compute = [&](int buf) {
        #pragma unroll
        for (int kk = 0; kk < 16; kk += 8) {
            uint32_t af[2][4];
            #pragma unroll
            for (int mt = 0; mt < 2; mt++) {
                int r = wm * 32 + mt * 16;
                af[mt][0] = As[buf][(r + g) * LDA_S + kk + t];
                af[mt][1] = As[buf][(r + g + 8) * LDA_S + kk + t];
                af[mt][2] = As[buf][(r + g) * LDA_S + kk + t + 4];
                af[mt][3] = As[buf][(r + g + 8) * LDA_S + kk + t + 4];
            }
            uint32_t bf[8][2];
            #pragma unroll
            for (int nt = 0; nt < 8; nt++) {
                int n = wn * 64 + nt * 8 + g;
                if (TRANSB) {
                    bf[nt][0] = Bs[buf][n * LDB1 + kk + t];
                    bf[nt][1] = Bs[buf][n * LDB1 + kk + t + 4];
                } else {
                    bf[nt][0] = Bs[buf][(kk + t) * LDB0 + n];
                    bf[nt][1] = Bs[buf][(kk + t + 4) * LDB0 + n];
                }
            }
            #pragma unroll
            for (int mt = 0; mt < 2; mt++)
                #pragma unroll
                for (int nt = 0; nt < 8; nt++)
                    MMA_TF32(acc[mt][nt], af[mt], bf[nt]);
        }
    };

    g_load(0);
    s_store(0);
    __syncthreads();
    int buf = 0;
    for (int k0 = 16; k0 < K; k0 += 16) {
        g_load(k0);
        compute(buf);
        s_store(buf ^ 1);
        __syncthreads();
        buf ^= 1;
    }
    compute(buf);

    #pragma unroll
    for (int mt = 0; mt < 2; mt++) {
        int r0 = i0 + wm * 32 + mt * 16 + g;
        #pragma unroll
        for (int nt = 0; nt < 8; nt++) {
            int c = j0 + wn * 64 + nt * 8 + 2 * t;
            if (c >= N) continue;
            float bx0 = 0.f, bx1 = 0.f;
            if (BIAS) { bx0 = bias[c]; bx1 = bias[c + 1]; }
            float2 v0 = make_float2(acc[mt][nt][0] + bx0, acc[mt][nt][1] + bx1);
            float2 v1 = make_float2(acc[mt][nt][2] + bx0, acc[mt][nt][3] + bx1);
            if (r0 < M)     *(float2*)(C + (size_t)r0 * ldc + c) = v0;
            if (r0 + 8 < M) *(float2*)(C + (size_t)(r0 + 8) * ldc + c) = v1;
        }
    }
}

// ---------------- channel attention ----------------
__global__ void k_attmax(int b) {
    __shared__ float red[256];
    float m[NLAYERS] = {0.f, 0.f, 0.f, 0.f, 0.f};
    const float* f = g_feats[b];
    for (int r = blockIdx.x; r < NN_NODE; r += gridDim.x) {
        #pragma unroll
        for (int c = 0; c < NLAYERS; c++)
            m[c] = fmaxf(m[c], f[(size_t)r * KTOT + c * FDIM + threadIdx.x]);
    }
    for (int c = 0; c < NLAYERS; c++) {
        red[threadIdx.x] = m[c];
        __syncthreads();
        for (int o = 128; o > 0; o >>= 1) {
            if (threadIdx.x < o) red[threadIdx.x] = fmaxf(red[threadIdx.x], red[threadIdx.x + o]);
            __syncthreads();
        }
        if (threadIdx.x == 0)
            atomicMax((int*)&g_amax[b][c], __float_as_int(red[0]));
        __syncthreads();
    }
}

__global__ void k_attfc(const float* __restrict__ fc1w, const float* __restrict__ fc1b,
                        const float* __restrict__ fc2w, const float* __restrict__ fc2b, int b) {
    if (threadIdx.x == 0 && blockIdx.x == 0) {
        float a[NLAYERS];
        for (int c = 0; c < NLAYERS; c++) a[c] = g_amax[b][c];
        float t[5 * NLAYERS];
        for (int j = 0; j < 5 * NLAYERS; j++) {
            float s = fc1b[j];
            for (int c = 0; c < NLAYERS; c++) s += fc1w[j * NLAYERS + c] * a[c];
            t[j] = fmaxf(s, 0.f);
        }
        for (int c = 0; c < NLAYERS; c++) {
            float s = fc2b[c];
            for (int j = 0; j < 5 * NLAYERS; j++) s += fc2w[c * (5 * NLAYERS) + j] * t[j];
            g_atts[b][c] = 1.0f / (1.0f + expf(-s));
        }
    }
}

__global__ void k_weff(const float* __restrict__ cw, int b) {
    int idx = blockIdx.x * blockDim.x + threadIdx.x;
    if (idx < OC * KTOT) {
        int c = (idx % KTOT) >> 8;
        g_weff[b][idx] = cw[idx] * g_atts[b][c];
    }
}

// ---------------- launch ----------------
extern "C" void kernel_launch(void* const* d_in, const int* in_sizes, int n_in,
                              void* d_out, int out_size) {
    const float* x_m    = (const float*)d_in[0];
    const float* x_d    = (const float*)d_in[1];
    const float* w_m    = (const float*)d_in[2];
    const float* w_d    = (const float*)d_in[3];
    const float* Wx     = (const float*)d_in[4];
    const float* bx     = (const float*)d_in[5];
    const float* Wy     = (const float*)d_in[6];
    const float* by     = (const float*)d_in[7];
    const float* fc1x_w = (const float*)d_in[8];
    const float* fc1x_b = (const float*)d_in[9];
    const float* fc2x_w = (const float*)d_in[10];
    const float* fc2x_b = (const float*)d_in[11];
    const float* fc1y_w = (const float*)d_in[12];
    const float* fc1y_b = (const float*)d_in[13];
    const float* fc2y_w = (const float*)d_in[14];
    const float* fc2y_b = (const float*)d_in[15];
    const float* cnnx_w = (const float*)d_in[16];
    const float* cnnx_b = (const float*)d_in[17];
    const float* cnny_w = (const float*)d_in[18];
    const float* cnny_b = (const float*)d_in[19];
    const int*   edges_m = (const int*)d_in[20];
    const int*   edges_d = (const int*)d_in[21];
    float* out = (float*)d_out;

    float *p_h1, *p_feats, *p_weff, *p_emb;
    cudaGetSymbolAddress((void**)&p_h1,    g_h1);
    cudaGetSymbolAddress((void**)&p_feats, g_feats);
    cudaGetSymbolAddress((void**)&p_weff,  g_weff);
    cudaGetSymbolAddress((void**)&p_emb,   g_emb);

    const int MT = (NN_NODE + 127) / 128;   // 79

    k_init<<<(NN_NODE + 255) / 256, 256>>>();

    for (int b = 0; b < 2; b++) {
        const int*   edges = b ? edges_d : edges_m;
        const float* w     = b ? w_d : w_m;
        const float* W     = b ? Wy : Wx;
        const float* bias  = b ? by : bx;
        const float* fc1w  = b ? fc1y_w : fc1x_w;
        const float* fc1b  = b ? fc1y_b : fc1x_b;
        const float* fc2w  = b ? fc2y_w : fc2x_w;
        const float* fc2b  = b ? fc2y_b : fc2x_b;
        const float* cw    = b ? cnny_w : cnnx_w;
        const float* cb    = b ? cnny_b : cnnx_b;
        float* featsB = p_feats + (size_t)b * NN_NODE * KTOT;

        k_deg_cnt<<<E_NUM / 256, 256>>>(edges, w, b);
        k_rsqrt<<<(NN_NODE + 255) / 256, 256>>>(b);
        k_scan<<<1, 1024>>>(b);
        k_fill<<<E_NUM / 256, 256>>>(edges, w, b);

        const float* hin = b ? x_d : x_m;
        int lda = FDIM;
        for (int i = 0; i < NLAYERS; i++) {
            k_gemm_tf32<0, 0><<<dim3(FDIM / 128, MT), 256>>>(
                NN_NODE, FDIM, FDIM, hin, lda, W + (size_t)i * FDIM * FDIM, FDIM,
                p_h1, FDIM, nullptr);
            k_aggregate<<<NN_NODE, 256>>>(p_h1, b, bias + (size_t)i * FDIM, i);
            hin = featsB + (size_t)i * FDIM;
            lda = KTOT;
        }

        k_attmax<<<256, 256>>>(b);
        k_attfc<<<1, 32>>>(fc1w, fc1b, fc2w, fc2b, b);
        k_weff<<<(OC * KTOT + 255) / 256, 256>>>(cw, b);

        k_gemm_tf32<1, 1><<<dim3(1, MT), 256>>>(
            NN_NODE, OC, KTOT, featsB, KTOT,
            p_weff + (size_t)b * OC * KTOT, KTOT,
            p_emb + (size_t)b * NN_NODE * OC, OC, cb);
    }

    k_gemm_tf32<1, 0><<<dim3(MT, MT), 256>>>(
        NN_NODE, NN_NODE, OC,
        p_emb, OC,
        p_emb + (size_t)NN_NODE * OC, OC,
        out, NN_NODE, nullptr);
}

// round 3
// speedup vs baseline: 2.4753x; 1.1688x over previous
#include <cuda_runtime.h>
#include <math.h>
#include <stdint.h>

#define NN_NODE 10000
#define E_NUM   320000
#define FDIM    256
#define NLAYERS 5
#define OC      128
#define KTOT    (NLAYERS*FDIM)   // 1280

// ---------------- scratch (no allocation allowed) ----------------
__device__ float g_dinv[2][NN_NODE];
__device__ int   g_cnt[2][NN_NODE];
__device__ int   g_rowptr[2][NN_NODE + 1];
__device__ int   g_csr_src[2][E_NUM];
__device__ float g_csr_norm[2][E_NUM];
__device__ __align__(16) float g_feats[2][(size_t)NN_NODE * KTOT];
__device__ __align__(16) float g_h1[2][(size_t)NN_NODE * FDIM];
__device__ float g_amax[2][NLAYERS];
__device__ float g_atts[2][NLAYERS];
__device__ __align__(16) float g_weff[2][OC * KTOT];
__device__ __align__(16) float g_emb[2][(size_t)NN_NODE * OC];

// ---------------- streams/events created once, before harness checkpoints ----------------
struct HxRes {
    cudaStream_t s0, s1;
    cudaEvent_t ev_fork, ev_j0, ev_j1;
    HxRes() {
        cudaStreamCreateWithFlags(&s0, cudaStreamNonBlocking);
        cudaStreamCreateWithFlags(&s1, cudaStreamNonBlocking);
        cudaEventCreateWithFlags(&ev_fork, cudaEventDisableTiming);
        cudaEventCreateWithFlags(&ev_j0, cudaEventDisableTiming);
        cudaEventCreateWithFlags(&ev_j1, cudaEventDisableTiming);
    }
};
static HxRes g_hx;

// ---------------- small prep kernels ----------------
__global__ void k_init() {
    int i = blockIdx.x * blockDim.x + threadIdx.x;
    if (i < NN_NODE) {
        g_dinv[0][i] = 1.0f; g_dinv[1][i] = 1.0f;
        g_cnt[0][i] = 0;     g_cnt[1][i] = 0;
    }
    if (i < NLAYERS) { g_amax[0][i] = 0.0f; g_amax[1][i] = 0.0f; }
}

__global__ void k_deg_cnt(const int* __restrict__ edges, const float* __restrict__ w, int b) {
    int e = blockIdx.x * blockDim.x + threadIdx.x;
    if (e < E_NUM) {
        int dst = edges[E_NUM + e];
        atomicAdd(&g_dinv[b][dst], w[e]);
        atomicAdd(&g_cnt[b][dst], 1);
    }
}

__global__ void k_rsqrt(int b) {
    int i = blockIdx.x * blockDim.x + threadIdx.x;
    if (i < NN_NODE) g_dinv[b][i] = rsqrtf(g_dinv[b][i]);
}

// coalesced chunked exclusive scan of g_cnt -> g_rowptr; resets g_cnt
__global__ void k_scan(int b) {
    __shared__ int wsum[32];
    __shared__ int chunk_base;
    int tid = threadIdx.x, lane = tid & 31, w = tid >> 5;
    if (tid == 0) chunk_base = 0;
    __syncthreads();
    for (int c0 = 0; c0 < NN_NODE; c0 += 1024) {
        int idx = c0 + tid;
        int v = (idx < NN_NODE) ? g_cnt[b][idx] : 0;
        int sc = v;
        #pragma unroll
        for (int off = 1; off < 32; off <<= 1) {
            int u = __shfl_up_sync(0xffffffffu, sc, off);
            if (lane >= off) sc += u;
        }
        if (lane == 31) wsum[w] = sc;
        __syncthreads();
        if (w == 0) {
            int t = wsum[lane];
            #pragma unroll
            for (int off = 1; off < 32; off <<= 1) {
                int u = __shfl_up_sync(0xffffffffu, t, off);
                if (lane >= off) t += u;
            }
            wsum[lane] = t;
        }
        __syncthreads();
        int total = wsum[31];
        int excl = chunk_base + (w ? wsum[w - 1] : 0) + sc - v;
        if (idx < NN_NODE) { g_rowptr[b][idx] = excl; g_cnt[b][idx] = 0; }
        __syncthreads();
        if (tid == 0) chunk_base += total;
        __syncthreads();
    }
    if (tid == 0) g_rowptr[b][NN_NODE] = chunk_base;
}

__global__ void k_fill(const int* __restrict__ edges, const float* __restrict__ w, int b) {
    int e = blockIdx.x * blockDim.x + threadIdx.x;
    if (e < E_NUM) {
        int s = edges[e];
        int d = edges[E_NUM + e];
        int pos = g_rowptr[b][d] + atomicAdd(&g_cnt[b][d], 1);
        g_csr_src[b][pos] = s;
        g_csr_norm[b][pos] = g_dinv[b][s] * w[e] * g_dinv[b][d];
    }
}

// ---------------- aggregation (+ fused global max pool per layer) ----------------
__global__ void k_aggregate(const float* __restrict__ h1, int b,
                            const float* __restrict__ bias, int layer) {
    __shared__ float red[8];
    int v = blockIdx.x;
    int f = threadIdx.x;
    float dv = g_dinv[b][v];
    float acc = dv * dv * h1[(size_t)v * FDIM + f];
    int e = g_rowptr[b][v];
    int e2 = g_rowptr[b][v + 1];
    const int*   srcs  = g_csr_src[b];
    const float* norms = g_csr_norm[b];
    for (; e + 4 <= e2; e += 4) {
        int u0 = srcs[e], u1 = srcs[e + 1], u2 = srcs[e + 2], u3 = srcs[e + 3];
        float n0 = norms[e], n1 = norms[e + 1], n2 = norms[e + 2], n3 = norms[e + 3];
        float a0 = h1[(size_t)u0 * FDIM + f];
        float a1 = h1[(size_t)u1 * FDIM + f];
        float a2 = h1[(size_t)u2 * FDIM + f];
        float a3 = h1[(size_t)u3 * FDIM + f];
        acc += n0 * a0 + n1 * a1 + n2 * a2 + n3 * a3;
    }
    for (; e < e2; e++) acc += norms[e] * h1[(size_t)srcs[e] * FDIM + f];
    acc += bias[f];
    float val = fmaxf(acc, 0.0f);
    g_feats[b][(size_t)v * KTOT + layer * FDIM + f] = val;

    // fused max pool: block max -> atomicMax (values >= 0)
    float m = val;
    #pragma unroll
    for (int off = 16; off > 0; off >>= 1)
        m = fmaxf(m, __shfl_xor_sync(0xffffffffu, m, off));
    if ((f & 31) == 0) red[f >> 5] = m;
    __syncthreads();
    if (f < 8) {
        m = red[f];
        #pragma unroll
        for (int off = 4; off > 0; off >>= 1)
            m = fmaxf(m, __shfl_xor_sync(0xffu, m, off));
        if (f == 0) atomicMax((int*)&g_amax[b][layer], __float_as_int(m));
    }
}

// ---------------- TF32 tensor-core GEMM 128x128x16 ----------------
__device__ __forceinline__ uint32_t f2tf(float x) {
    uint32_t u; asm("cvt.rna.tf32.f32 %0, %1;" : "=r"(u) : "f"(x)); return u;
}

#define MMA_TF32(d, a, b) \
  asm volatile("mma.sync.aligned.m16n8k8.row.col.f32.tf32.tf32.f32 " \
      "{%0,%1,%2,%3}, {%4,%5,%6,%7}, {%8,%9}, {%0,%1,%2,%3};" \
      : "+f"(d[0]), "+f"(d[1]), "+f"(d[2]), "+f"(d[3]) \
      : "r"(a[0]), "r"(a[1]), "r"(a[2]), "r"(a[3]), "r"(b[0]), "r"(b[1]))

// A [M,K] row-major. TRANSB=0: B [K,N] (N multiple of 128). TRANSB=1: B [N,K].
// K multiple of 16.
template <int TRANSB, int BIAS>
__global__ __launch_bounds__(256) void k_gemm_tf32(
        int M, int N, int K,
        const float* __restrict__ A, int lda,
        const float* __restrict__ B, int ldb,
        float* __restrict__ C, int ldc,
        const float* __restrict__ bias) {
    constexpr int LDA_S = 20;
    constexpr int LDB0  = 136;
    constexpr int LDB1  = 20;
    __shared__ uint32_t As[2][128 * LDA_S];
    __shared__ uint32_t Bs[2][TRANSB ? 128 * LDB1 : 16 * LDB0];

    const int tid = threadIdx.x;
    const int wid = tid >> 5;
    const int lane = tid & 31;
    const int g = lane >> 2, t = lane & 3;
    const int wm = wid >> 1, wn = wid & 1;
    const int i0 = blockIdx.y * 128, j0 = blockIdx.x * 128;

    const int ar  = tid >> 1, akc = (tid & 1) * 8;
    const int bkr = tid >> 4, bnc = (tid & 15) * 8;

    float acc[2][8][4];
    #pragma unroll
    for (int mt = 0; mt < 2; mt++)
        #pragma unroll
        for (int nt = 0; nt < 8; nt++)
            #pragma unroll
            for (int q = 0; q < 4; q++) acc[mt][nt][q] = 0.0f;

    float4 a0v, a1v, b0v, b1v;
    const float4 z4 = make_float4(0.f, 0.f, 0.f, 0.f);

    auto g_load = [&](int k0) {
        a0v = z4; a1v = z4;
        if (i0 + ar < M) {
            const float* p = A + (size_t)(i0 + ar) * lda + k0 + akc;
            a0v = *(const float4*)p;
            a1v = *(const float4*)(p + 4);
        }
        if (TRANSB) {
            b0v = z4; b1v = z4;
            if (j0 + ar < N) {
                const float* p = B + (size_t)(j0 + ar) * ldb + k0 + akc;
                b0v = *(const float4*)p;
                b1v = *(const float4*)(p + 4);
            }
        } else {
            const float* p = B + (size_t)(k0 + bkr) * ldb + j0 + bnc;
            b0v = *(const float4*)p;
            b1v = *(const float4*)(p + 4);
        }
    };

    auto s_store = [&](int buf) {
        uint4 u0 = make_uint4(f2tf(a0v.x), f2tf(a0v.y), f2tf(a0v.z), f2tf(a0v.w));
        uint4 u1 = make_uint4(f2tf(a1v.x), f2tf(a1v.y), f2tf(a1v.z), f2tf(a1v.w));
        *(uint4*)&As[buf][ar * LDA_S + akc]     = u0;
        *(uint4*)&As[buf][ar * LDA_S + akc + 4] = u1;
        uint4 v0 = make_uint4(f2tf(b0v.x), f2tf(b0v.y), f2tf(b0v.z), f2tf(b0v.w));
        uint4 v1 = make_uint4(f2tf(b1v.x), f2tf(b1v.y), f2tf(b1v.z), f2tf(b1v.w));
        if (TRANSB) {
            *(uint4*)&Bs[buf][ar * LDB1 + akc]     = v0;
            *(uint4*)&Bs[buf][ar * LDB1 + akc + 4] = v1;
        } else {
            *(uint4*)&Bs[buf][bkr * LDB0 + bnc]     = v0;
            *(uint4*)&Bs[buf][bkr * LDB0 + bnc + 4] = v1;
        }
    };

    auto compute = [&](int buf) {
        #pragma unroll
        for (int kk = 0; kk < 16; kk += 8) {
            uint32_t af[2][4];
            #pragma unroll
            for (int mt = 0; mt < 2; mt++) {
                int r = wm * 32 + mt * 16;
                af[mt][0] = As[buf][(r + g) * LDA_S + kk + t];
                af[mt][1] = As[buf][(r + g + 8) * LDA_S + kk + t];
                af[mt][2] = As[buf][(r + g) * LDA_S + kk + t + 4];
                af[mt][3] = As[buf][(r + g + 8) * LDA_S + kk + t + 4];
            }
            uint32_t bf[8][2];
            #pragma unroll
            for (int nt = 0; nt < 8; nt++) {
                int n = wn * 64 + nt * 8 + g;
                if (TRANSB) {
                    bf[nt][0] = Bs[buf][n * LDB1 + kk + t];
                    bf[nt][1] = Bs[buf][n * LDB1 + kk + t + 4];
                } else {
                    bf[nt][0] = Bs[buf][(kk + t) * LDB0 + n];
                    bf[nt][1] = Bs[buf][(kk + t + 4) * LDB0 + n];
                }
            }
            #pragma unroll
            for (int mt = 0; mt < 2; mt++)
                #pragma unroll
                for (int nt = 0; nt < 8; nt++)
                    MMA_TF32(acc[mt][nt], af[mt], bf[nt]);
        }
    };

    g_load(0);
    s_store(0);
    __syncthreads();
    int buf = 0;
    for (int k0 = 16; k0 < K; k0 += 16) {
        g_load(k0);
        compute(buf);
        s_store(buf ^ 1);
        __syncthreads();
        buf ^= 1;
    }
    compute(buf);

    #pragma unroll
    for (int mt = 0; mt < 2; mt++) {
        int r0 = i0 + wm * 32 + mt * 16 + g;
        #pragma unroll
        for (int nt = 0; nt < 8; nt++) {
            int c = j0 + wn * 64 + nt * 8 + 2 * t;
            if (c >= N) continue;
            float bx0 = 0.f, bx1 = 0.f;
            if (BIAS) { bx0 = bias[c]; bx1 = bias[c + 1]; }
            float2 v0 = make_float2(acc[mt][nt][0] + bx0, acc[mt][nt][1] + bx1);
            float2 v1 = make_float2(acc[mt][nt][2] + bx0, acc[mt][nt][3] + bx1);
            if (r0 < M)     *(float2*)(C + (size_t)r0 * ldc + c) = v0;
            if (r0 + 8 < M) *(float2*)(C + (size_t)(r0 + 8) * ldc + c) = v1;
        }
    }
}

// ---------------- attention FC + effective conv weights ----------------
__global__ void k_attfc(const float* __restrict__ fc1w, const float* __restrict__ fc1b,
                        const float* __restrict__ fc2w, const float* __restrict__ fc2b, int b) {
    if (threadIdx.x == 0 && blockIdx.x == 0) {
        float a[NLAYERS];
        for (int c = 0; c < NLAYERS; c++) a[c] = g_amax[b][c];
        float t[5 * NLAYERS];
        for (int j = 0; j < 5 * NLAYERS; j++) {
            float s = fc1b[j];
            for (int c = 0; c < NLAYERS; c++) s += fc1w[j * NLAYERS + c] * a[c];
            t[j] = fmaxf(s, 0.f);
        }
        for (int c = 0; c < NLAYERS; c++) {
            float s = fc2b[c];
            for (int j = 0; j < 5 * NLAYERS; j++) s += fc2w[c * (5 * NLAYERS) + j] * t[j];
            g_atts[b][c] = 1.0f / (1.0f + expf(-s));
        }
    }
}

__global__ void k_weff(const float* __restrict__ cw, int b) {
    int idx = blockIdx.x * blockDim.x + threadIdx.x;
    if (idx < OC * KTOT) {
        int c = (idx % KTOT) >> 8;
        g_weff[b][idx] = cw[idx] * g_atts[b][c];
    }
}

// ---------------- launch ----------------
extern "C" void kernel_launch(void* const* d_in, const int* in_sizes, int n_in,
                              void* d_out, int out_size) {
    const float* x_m    = (const float*)d_in[0];
    const float* x_d    = (const float*)d_in[1];
    const float* w_m    = (const float*)d_in[2];
    const float* w_d    = (const float*)d_in[3];
    const float* Wx     = (const float*)d_in[4];
    const float* bx     = (const float*)d_in[5];
    const float* Wy     = (const float*)d_in[6];
    const float* by     = (const float*)d_in[7];
    const float* fc1x_w = (const float*)d_in[8];
    const float* fc1x_b = (const float*)d_in[9];
    const float* fc2x_w = (const float*)d_in[10];
    const float* fc2x_b = (const float*)d_in[11];
    const float* fc1y_w = (const float*)d_in[12];
    const float* fc1y_b = (const float*)d_in[13];
    const float* fc2y_w = (const float*)d_in[14];
    const float* fc2y_b = (const float*)d_in[15];
    const float* cnnx_w = (const float*)d_in[16];
    const float* cnnx_b = (const float*)d_in[17];
    const float* cnny_w = (const float*)d_in[18];
    const float* cnny_b = (const float*)d_in[19];
    const int*   edges_m = (const int*)d_in[20];
    const int*   edges_d = (const int*)d_in[21];
    float* out = (float*)d_out;

    float *p_h1, *p_feats, *p_weff, *p_emb;
    cudaGetSymbolAddress((void**)&p_h1,    g_h1);
    cudaGetSymbolAddress((void**)&p_feats, g_feats);
    cudaGetSymbolAddress((void**)&p_weff,  g_weff);
    cudaGetSymbolAddress((void**)&p_emb,   g_emb);

    const int MT = (NN_NODE + 127) / 128;   // 79

    k_init<<<(NN_NODE + 255) / 256, 256>>>();
    cudaEventRecord(g_hx.ev_fork, 0);
    cudaStreamWaitEvent(g_hx.s0, g_hx.ev_fork, 0);
    cudaStreamWaitEvent(g_hx.s1, g_hx.ev_fork, 0);

    for (int b = 0; b < 2; b++) {
        cudaStream_t st = b ? g_hx.s1 : g_hx.s0;
        const int*   edges = b ? edges_d : edges_m;
        const float* w     = b ? w_d : w_m;
        const float* W     = b ? Wy : Wx;
        const float* bias  = b ? by : bx;
        const float* fc1w  = b ? fc1y_w : fc1x_w;
        const float* fc1b  = b ? fc1y_b : fc1x_b;
        const float* fc2w  = b ? fc2y_w : fc2x_w;
        const float* fc2b  = b ? fc2y_b : fc2x_b;
        const float* cw    = b ? cnny_w : cnnx_w;
        const float* cb    = b ? cnny_b : cnnx_b;
        float* featsB = p_feats + (size_t)b * NN_NODE * KTOT;
        float* h1B    = p_h1    + (size_t)b * NN_NODE * FDIM;

        k_deg_cnt<<<E_NUM / 256, 256, 0, st>>>(edges, w, b);
        k_rsqrt<<<(NN_NODE + 255) / 256, 256, 0, st>>>(b);
        k_scan<<<1, 1024, 0, st>>>(b);
        k_fill<<<E_NUM / 256, 256, 0, st>>>(edges, w, b);

        const float* hin = b ? x_d : x_m;
        int lda = FDIM;
        for (int i = 0; i < NLAYERS; i++) {
            k_gemm_tf32<0, 0><<<dim3(FDIM / 128, MT), 256, 0, st>>>(
                NN_NODE, FDIM, FDIM, hin, lda, W + (size_t)i * FDIM * FDIM, FDIM,
                h1B, FDIM, nullptr);
            k_aggregate<<<NN_NODE, 256, 0, st>>>(h1B, b, bias + (size_t)i * FDIM, i);
            hin = featsB + (size_t)i * FDIM;
            lda = KTOT;
        }

        k_attfc<<<1, 32, 0, st>>>(fc1w, fc1b, fc2w, fc2b, b);
        k_weff<<<(OC * KTOT + 255) / 256, 256, 0, st>>>(cw, b);

        k_gemm_tf32<1, 1><<<dim3(1, MT), 256, 0, st>>>(
            NN_NODE, OC, KTOT, featsB, KTOT,
            p_weff + (size_t)b * OC * KTOT, KTOT,
            p_emb + (size_t)b * NN_NODE * OC, OC, cb);
    }

    cudaEventRecord(g_hx.ev_j0, g_hx.s0);
    cudaEventRecord(g_hx.ev_j1, g_hx.s1);
    cudaStreamWaitEvent(0, g_hx.ev_j0, 0);
    cudaStreamWaitEvent(0, g_hx.ev_j1, 0);

    k_gemm_tf32<1, 0><<<dim3(MT, MT), 256>>>(
        NN_NODE, NN_NODE, OC,
        p_emb, OC,
        p_emb + (size_t)NN_NODE * OC, OC,
        out, NN_NODE, nullptr);
}

// round 5
// speedup vs baseline: 3.5765x; 1.4449x over previous
#include <cuda_runtime.h>
#include <math.h>
#include <stdint.h>

#define NN_NODE 10000
#define E_NUM   320000
#define FDIM    256
#define NLAYERS 5
#define OC      128
#define KTOT    (NLAYERS*FDIM)   // 1280

// ---------------- scratch ----------------
__device__ float g_dinv[2][NN_NODE];
__device__ int   g_cnt[2][NN_NODE];
__device__ int   g_rowptr[2][NN_NODE + 1];
__device__ int   g_csr_src[2][E_NUM];
__device__ float g_csr_norm[2][E_NUM];
__device__ __align__(16) float g_feats[2][(size_t)NN_NODE * KTOT];
__device__ __align__(16) float g_h1[2][(size_t)NN_NODE * FDIM];
__device__ __align__(16) float g_xr[2][(size_t)NN_NODE * FDIM];     // tf32-rounded inputs
__device__ __align__(16) float g_wr[2][(size_t)NLAYERS * FDIM * FDIM]; // tf32-rounded weights
__device__ float g_amax[2][NLAYERS];
__device__ float g_atts[2][NLAYERS];
__device__ __align__(16) float g_weff[2][OC * KTOT];
__device__ __align__(16) float g_emb[2][(size_t)NN_NODE * OC];

__device__ __forceinline__ uint32_t f2tf(float x) {
    uint32_t u; asm("cvt.rna.tf32.f32 %0, %1;" : "=r"(u) : "f"(x)); return u;
}
__device__ __forceinline__ float f2tff(float x) { return __uint_as_float(f2tf(x)); }

// ---------------- TF32 cp.async GEMM 128x128x16, 3-stage ----------------
#define MMA_TF32(d, a, b) \
  asm volatile("mma.sync.aligned.m16n8k8.row.col.f32.tf32.tf32.f32 " \
      "{%0,%1,%2,%3}, {%4,%5,%6,%7}, {%8,%9}, {%0,%1,%2,%3};" \
      : "+f"(d[0]), "+f"(d[1]), "+f"(d[2]), "+f"(d[3]) \
      : "r"(a[0]), "r"(a[1]), "r"(a[2]), "r"(a[3]), "r"(b[0]), "r"(b[1]))

__device__ __forceinline__ void cp16(uint32_t d, const void* s, bool p) {
    int sz = p ? 16 : 0;
    asm volatile("cp.async.cg.shared.global [%0], [%1], 16, %2;\n" :: "r"(d), "l"(s), "r"(sz));
}
__device__ __forceinline__ void cp_commit() { asm volatile("cp.async.commit_group;\n"); }
template <int N> __device__ __forceinline__ void cp_wait() {
    asm volatile("cp.async.wait_group %0;\n" :: "n"(N));
}

// A [M,K] rm (pre-rounded tf32). TRANSB=0: B [K,N] (N mult 128). TRANSB=1: B [N,K].
// K mult of 16. ROUND_OUT: write tf32-rounded. STREAM_OUT: use st.cs.
template <int TRANSB, int BIAS, int ROUND_OUT, int STREAM_OUT>
__global__ __launch_bounds__(256) void k_gemm_tf32(
        int M, int N, int K,
        const float* __restrict__ A, int lda,
        const float* __restrict__ B, int ldb,
        float* __restrict__ C, int ldc,
        const float* __restrict__ bias) {
    constexpr int STAGES = 3;
    constexpr int LDA_S = 20;
    constexpr int LDB0  = 136;
    constexpr int LDB1  = 20;
    constexpr int A_ST  = 128 * LDA_S;
    constexpr int B_ST  = TRANSB ? 128 * LDB1 : 16 * LDB0;
    extern __shared__ uint32_t smem[];
    uint32_t* As = smem;
    uint32_t* Bs = smem + STAGES * A_ST;

    const int tid = threadIdx.x;
    const int wid = tid >> 5;
    const int lane = tid & 31;
    const int g = lane >> 2, t = lane & 3;
    const int wm = wid >> 1, wn = wid & 1;
    const int i0 = blockIdx.y * 128, j0 = blockIdx.x * 128;

    const int ar  = tid >> 1, akc = (tid & 1) * 8;
    const int bkr = tid >> 4, bnc = (tid & 15) * 8;

    const bool a_ok = (i0 + ar < M);
    const float* a_src = A + (size_t)(a_ok ? i0 + ar : M - 1) * lda + akc;
    const bool b_ok = TRANSB ? (j0 + ar < N) : true;
    const float* b_src = TRANSB
        ? B + (size_t)(b_ok ? j0 + ar : N - 1) * ldb + akc
        : B + (size_t)bkr * ldb + j0 + bnc;

    uint32_t sa_base = (uint32_t)__cvta_generic_to_shared(&As[ar * LDA_S + akc]);
    uint32_t sb_base = TRANSB
        ? (uint32_t)__cvta_generic_to_shared(&Bs[ar * LDB1 + akc])
        : (uint32_t)__cvta_generic_to_shared(&Bs[bkr * LDB0 + bnc]);

    auto issue = [&](int s, int k0) {
        uint32_t da = sa_base + s * (A_ST * 4);
        const float* pa = a_src + k0;
        cp16(da,      pa,     a_ok);
        cp16(da + 16, pa + 4, a_ok);
        uint32_t db = sb_base + s * (B_ST * 4);
        const float* pb = TRANSB ? (b_src + k0) : (b_src + (size_t)k0 * ldb);
        cp16(db,      pb,     b_ok);
        cp16(db + 16, pb + 4, b_ok);
        cp_commit();
    };

    float acc[2][8][4];
    #pragma unroll
    for (int mt = 0; mt < 2; mt++)
        #pragma unroll
        for (int nt = 0; nt < 8; nt++)
            #pragma unroll
            for (int q = 0; q < 4; q++) acc[mt][nt][q] = 0.0f;

    auto compute = [&](int s) {
        const uint32_t* Ab = As + s * A_ST;
        const uint32_t* Bb = Bs + s * B_ST;
        #pragma unroll
        for (int kk = 0; kk < 16; kk += 8) {
            uint32_t af[2][4];
            #pragma unroll
            for (int mt = 0; mt < 2; mt++) {
                int r = wm * 32 + mt * 16;
                af[mt][0] = Ab[(r + g) * LDA_S + kk + t];
                af[mt][1] = Ab[(r + g + 8) * LDA_S + kk + t];
                af[mt][2] = Ab[(r + g) * LDA_S + kk + t + 4];
                af[mt][3] = Ab[(r + g + 8) * LDA_S + kk + t + 4];
            }
            uint32_t bf[8][2];
            #pragma unroll
            for (int nt = 0; nt < 8; nt++) {
                int n = wn * 64 + nt * 8 + g;
                if (TRANSB) {
                    bf[nt][0] = Bb[n * LDB1 + kk + t];
                    bf[nt][1] = Bb[n * LDB1 + kk + t + 4];
                } else {
                    bf[nt][0] = Bb[(kk + t) * LDB0 + n];
                    bf[nt][1] = Bb[(kk + t + 4) * LDB0 + n];
                }
            }
            #pragma unroll
            for (int mt = 0; mt < 2; mt++)
                #pragma unroll
                for (int nt = 0; nt < 8; nt++)
                    MMA_TF32(acc[mt][nt], af[mt], bf[nt]);
        }
    };

    const int ktiles = K / 16;
    issue(0, 0);
    if (ktiles > 1) issue(1, 16);
    for (int i = 0; i < ktiles; i++) {
        // Group accounting: committed = min(i+2, ktiles). compute(i) needs group i
        // complete. For i <= ktiles-2, wait_group 1 leaves only group i+1 pending.
        // For the LAST iteration committed == i+1, so wait_group 1 would leave
        // group i itself pending -> must drain fully (this was the R4 corruption).
        if (i < ktiles - 1) cp_wait<STAGES - 2>(); else cp_wait<0>();
        __syncthreads();
        int pf = i + STAGES - 1;
        if (pf < ktiles) issue(pf % STAGES, pf * 16);
        compute(i % STAGES);
    }

    #pragma unroll
    for (int mt = 0; mt < 2; mt++) {
        int r0 = i0 + wm * 32 + mt * 16 + g;
        #pragma unroll
        for (int nt = 0; nt < 8; nt++) {
            int c = j0 + wn * 64 + nt * 8 + 2 * t;
            if (c >= N) continue;
            float bx0 = 0.f, bx1 = 0.f;
            if (BIAS) { bx0 = bias[c]; bx1 = bias[c + 1]; }
            float v00 = acc[mt][nt][0] + bx0, v01 = acc[mt][nt][1] + bx1;
            float v10 = acc[mt][nt][2] + bx0, v11 = acc[mt][nt][3] + bx1;
            if (ROUND_OUT) { v00 = f2tff(v00); v01 = f2tff(v01); v10 = f2tff(v10); v11 = f2tff(v11); }
            float2 p0 = make_float2(v00, v01);
            float2 p1 = make_float2(v10, v11);
            if (STREAM_OUT) {
                if (r0 < M)     __stcs((float2*)(C + (size_t)r0 * ldc + c), p0);
                if (r0 + 8 < M) __stcs((float2*)(C + (size_t)(r0 + 8) * ldc + c), p1);
            } else {
                if (r0 < M)     *(float2*)(C + (size_t)r0 * ldc + c) = p0;
                if (r0 + 8 < M) *(float2*)(C + (size_t)(r0 + 8) * ldc + c) = p1;
            }
        }
    }
}

// ---------------- streams/events/attrs created once ----------------
struct HxRes {
    cudaStream_t s0, s1;
    cudaEvent_t ev_fork, ev_j0, ev_j1;
    HxRes() {
        cudaStreamCreateWithFlags(&s0, cudaStreamNonBlocking);
        cudaStreamCreateWithFlags(&s1, cudaStreamNonBlocking);
        cudaEventCreateWithFlags(&ev_fork, cudaEventDisableTiming);
        cudaEventCreateWithFlags(&ev_j0, cudaEventDisableTiming);
        cudaEventCreateWithFlags(&ev_j1, cudaEventDisableTiming);
        cudaFuncSetAttribute((const void*)k_gemm_tf32<0,0,0,0>, cudaFuncAttributeMaxDynamicSharedMemorySize, 65536);
        cudaFuncSetAttribute((const void*)k_gemm_tf32<1,1,1,0>, cudaFuncAttributeMaxDynamicSharedMemorySize, 65536);
        cudaFuncSetAttribute((const void*)k_gemm_tf32<1,0,0,1>, cudaFuncAttributeMaxDynamicSharedMemorySize, 65536);
    }
};
static HxRes g_hx;

// ---------------- prep kernels ----------------
__global__ void k_init() {
    int i = blockIdx.x * blockDim.x + threadIdx.x;
    if (i < NN_NODE) {
        g_dinv[0][i] = 1.0f; g_dinv[1][i] = 1.0f;
        g_cnt[0][i] = 0;     g_cnt[1][i] = 0;
    }
    if (i < NLAYERS) { g_amax[0][i] = 0.0f; g_amax[1][i] = 0.0f; }
}

__global__ void k_round_copy(const float* __restrict__ in, float* __restrict__ out, int n4) {
    int i = blockIdx.x * blockDim.x + threadIdx.x;
    if (i < n4) {
        float4 v = ((const float4*)in)[i];
        v.x = f2tff(v.x); v.y = f2tff(v.y); v.z = f2tff(v.z); v.w = f2tff(v.w);
        ((float4*)out)[i] = v;
    }
}

__global__ void k_deg_cnt(const int* __restrict__ edges, const float* __restrict__ w, int b) {
    int e = blockIdx.x * blockDim.x + threadIdx.x;
    if (e < E_NUM) {
        int dst = edges[E_NUM + e];
        atomicAdd(&g_dinv[b][dst], w[e]);
        atomicAdd(&g_cnt[b][dst], 1);
    }
}

__global__ void k_rsqrt(int b) {
    int i = blockIdx.x * blockDim.x + threadIdx.x;
    if (i < NN_NODE) g_dinv[b][i] = rsqrtf(g_dinv[b][i]);
}

__global__ void k_scan(int b) {
    __shared__ int wsum[32];
    __shared__ int chunk_base;
    int tid = threadIdx.x, lane = tid & 31, w = tid >> 5;
    if (tid == 0) chunk_base = 0;
    __syncthreads();
    for (int c0 = 0; c0 < NN_NODE; c0 += 1024) {
        int idx = c0 + tid;
        int v = (idx < NN_NODE) ? g_cnt[b][idx] : 0;
        int sc = v;
        #pragma unroll
        for (int off = 1; off < 32; off <<= 1) {
            int u = __shfl_up_sync(0xffffffffu, sc, off);
            if (lane >= off) sc += u;
        }
        if (lane == 31) wsum[w] = sc;
        __syncthreads();
        if (w == 0) {
            int tv = wsum[lane];
            #pragma unroll
            for (int off = 1; off < 32; off <<= 1) {
                int u = __shfl_up_sync(0xffffffffu, tv, off);
                if (lane >= off) tv += u;
            }
            wsum[lane] = tv;
        }
        __syncthreads();
        int total = wsum[31];
        int excl = chunk_base + (w ? wsum[w - 1] : 0) + sc - v;
        if (idx < NN_NODE) { g_rowptr[b][idx] = excl; g_cnt[b][idx] = 0; }
        __syncthreads();
        if (tid == 0) chunk_base += total;
        __syncthreads();
    }
    if (tid == 0) g_rowptr[b][NN_NODE] = chunk_base;
}

__global__ void k_fill(const int* __restrict__ edges, const float* __restrict__ w, int b) {
    int e = blockIdx.x * blockDim.x + threadIdx.x;
    if (e < E_NUM) {
        int s = edges[e];
        int d = edges[E_NUM + e];
        int pos = g_rowptr[b][d] + atomicAdd(&g_cnt[b][d], 1);
        g_csr_src[b][pos] = s;
        g_csr_norm[b][pos] = g_dinv[b][s] * w[e] * g_dinv[b][d];
    }
}

// ---------------- aggregation (float4, fused max pool, rounded output) ----------------
__global__ __launch_bounds__(64) void k_aggregate(const float* __restrict__ h1, int b,
                                                  const float* __restrict__ bias, int layer) {
    __shared__ float red2[2];
    int v = blockIdx.x;
    int t = threadIdx.x;                 // 0..63 (float4 lane)
    const float4* h1v = (const float4*)h1;
    float dv = g_dinv[b][v];
    float sw = dv * dv;
    float4 a = h1v[(size_t)v * 64 + t];
    float4 acc = make_float4(sw * a.x, sw * a.y, sw * a.z, sw * a.w);
    int e = g_rowptr[b][v];
    int e2 = g_rowptr[b][v + 1];
    const int*   srcs  = g_csr_src[b];
    const float* norms = g_csr_norm[b];
    for (; e + 4 <= e2; e += 4) {
        int u0 = srcs[e], u1 = srcs[e + 1], u2 = srcs[e + 2], u3 = srcs[e + 3];
        float n0 = norms[e], n1 = norms[e + 1], n2 = norms[e + 2], n3 = norms[e + 3];
        float4 x0 = h1v[(size_t)u0 * 64 + t];
        float4 x1 = h1v[(size_t)u1 * 64 + t];
        float4 x2 = h1v[(size_t)u2 * 64 + t];
        float4 x3 = h1v[(size_t)u3 * 64 + t];
        acc.x += n0 * x0.x + n1 * x1.x + n2 * x2.x + n3 * x3.x;
        acc.y += n0 * x0.y + n1 * x1.y + n2 * x2.y + n3 * x3.y;
        acc.z += n0 * x0.z + n1 * x1.z + n2 * x2.z + n3 * x3.z;
        acc.w += n0 * x0.w + n1 * x1.w + n2 * x2.w + n3 * x3.w;
    }
    for (; e < e2; e++) {
        float n = norms[e];
        float4 x = h1v[(size_t)srcs[e] * 64 + t];
        acc.x += n * x.x; acc.y += n * x.y; acc.z += n * x.z; acc.w += n * x.w;
    }
    float4 bv = ((const float4*)bias)[t];
    acc.x = fmaxf(acc.x + bv.x, 0.f);
    acc.y = fmaxf(acc.y + bv.y, 0.f);
    acc.z = fmaxf(acc.z + bv.z, 0.f);
    acc.w = fmaxf(acc.w + bv.w, 0.f);
    float4 rv = make_float4(f2tff(acc.x), f2tff(acc.y), f2tff(acc.z), f2tff(acc.w));
    *(float4*)&g_feats[b][(size_t)v * KTOT + layer * FDIM + t * 4] = rv;

    float m = fmaxf(fmaxf(rv.x, rv.y), fmaxf(rv.z, rv.w));
    #pragma unroll
    for (int off = 16; off > 0; off >>= 1)
        m = fmaxf(m, __shfl_xor_sync(0xffffffffu, m, off));
    if ((t & 31) == 0) red2[t >> 5] = m;
    __syncthreads();
    if (t == 0)
        atomicMax((int*)&g_amax[b][layer], __float_as_int(fmaxf(red2[0], red2[1])));
}

// ---------------- attention FC + effective conv weights ----------------
__global__ void k_attfc(const float* __restrict__ fc1w, const float* __restrict__ fc1b,
                        const float* __restrict__ fc2w, const float* __restrict__ fc2b, int b) {
    if (threadIdx.x == 0 && blockIdx.x == 0) {
        float a[NLAYERS];
        for (int c = 0; c < NLAYERS; c++) a[c] = g_amax[b][c];
        float t[5 * NLAYERS];
        for (int j = 0; j < 5 * NLAYERS; j++) {
            float s = fc1b[j];
            for (int c = 0; c < NLAYERS; c++) s += fc1w[j * NLAYERS + c] * a[c];
            t[j] = fmaxf(s, 0.f);
        }
        for (int c = 0; c < NLAYERS; c++) {
            float s = fc2b[c];
            for (int j = 0; j < 5 * NLAYERS; j++) s += fc2w[c * (5 * NLAYERS) + j] * t[j];
            g_atts[b][c] = 1.0f / (1.0f + expf(-s));
        }
    }
}

__global__ void k_weff(const float* __restrict__ cw, int b) {
    int idx = blockIdx.x * blockDim.x + threadIdx.x;
    if (idx < OC * KTOT) {
        int c = (idx % KTOT) >> 8;
        g_weff[b][idx] = f2tff(cw[idx] * g_atts[b][c]);
    }
}

// ---------------- launch ----------------
extern "C" void kernel_launch(void* const* d_in, const int* in_sizes, int n_in,
                              void* d_out, int out_size) {
    const float* x_m    = (const float*)d_in[0];
    const float* x_d    = (const float*)d_in[1];
    const float* w_m    = (const float*)d_in[2];
    const float* w_d    = (const float*)d_in[3];
    const float* Wx     = (const float*)d_in[4];
    const float* bx     = (const float*)d_in[5];
    const float* Wy     = (const float*)d_in[6];
    const float* by     = (const float*)d_in[7];
    const float* fc1x_w = (const float*)d_in[8];
    const float* fc1x_b = (const float*)d_in[9];
    const float* fc2x_w = (const float*)d_in[10];
    const float* fc2x_b = (const float*)d_in[11];
    const float* fc1y_w = (const float*)d_in[12];
    const float* fc1y_b = (const float*)d_in[13];
    const float* fc2y_w = (const float*)d_in[14];
    const float* fc2y_b = (const float*)d_in[15];
    const float* cnnx_w = (const float*)d_in[16];
    const float* cnnx_b = (const float*)d_in[17];
    const float* cnny_w = (const float*)d_in[18];
    const float* cnny_b = (const float*)d_in[19];
    const int*   edges_m = (const int*)d_in[20];
    const int*   edges_d = (const int*)d_in[21];
    float* out = (float*)d_out;

    float *p_h1, *p_feats, *p_weff, *p_emb, *p_xr, *p_wr;
    cudaGetSymbolAddress((void**)&p_h1,    g_h1);
    cudaGetSymbolAddress((void**)&p_feats, g_feats);
    cudaGetSymbolAddress((void**)&p_weff,  g_weff);
    cudaGetSymbolAddress((void**)&p_emb,   g_emb);
    cudaGetSymbolAddress((void**)&p_xr,    g_xr);
    cudaGetSymbolAddress((void**)&p_wr,    g_wr);

    const int MT = (NN_NODE + 127) / 128;   // 79
    const int SM_T0 = 3 * (128 * 20 + 16 * 136) * 4;  // TRANSB=0
    const int SM_T1 = 3 * (128 * 20 + 128 * 20) * 4;  // TRANSB=1

    k_init<<<(NN_NODE + 255) / 256, 256>>>();
    cudaEventRecord(g_hx.ev_fork, 0);
    cudaStreamWaitEvent(g_hx.s0, g_hx.ev_fork, 0);
    cudaStreamWaitEvent(g_hx.s1, g_hx.ev_fork, 0);

    for (int b = 0; b < 2; b++) {
        cudaStream_t st = b ? g_hx.s1 : g_hx.s0;
        const int*   edges = b ? edges_d : edges_m;
        const float* w     = b ? w_d : w_m;
        const float* W     = b ? Wy : Wx;
        const float* bias  = b ? by : bx;
        const float* fc1w  = b ? fc1y_w : fc1x_w;
        const float* fc1b  = b ? fc1y_b : fc1x_b;
        const float* fc2w  = b ? fc2y_w : fc2x_w;
        const float* fc2b  = b ? fc2y_b : fc2x_b;
        const float* cw    = b ? cnny_w : cnnx_w;
        const float* cb    = b ? cnny_b : cnnx_b;
        const float* x0    = b ? x_d : x_m;
        float* featsB = p_feats + (size_t)b * NN_NODE * KTOT;
        float* h1B    = p_h1    + (size_t)b * NN_NODE * FDIM;
        float* xrB    = p_xr    + (size_t)b * NN_NODE * FDIM;
        float* wrB    = p_wr    + (size_t)b * NLAYERS * FDIM * FDIM;

        k_round_copy<<<(NN_NODE * FDIM / 4 + 255) / 256, 256, 0, st>>>(x0, xrB, NN_NODE * FDIM / 4);
        k_round_copy<<<(NLAYERS * FDIM * FDIM / 4 + 255) / 256, 256, 0, st>>>(W, wrB, NLAYERS * FDIM * FDIM / 4);

        k_deg_cnt<<<E_NUM / 256, 256, 0, st>>>(edges, w, b);
        k_rsqrt<<<(NN_NODE + 255) / 256, 256, 0, st>>>(b);
        k_scan<<<1, 1024, 0, st>>>(b);
        k_fill<<<E_NUM / 256, 256, 0, st>>>(edges, w, b);

        const float* hin = xrB;
        int lda = FDIM;
        for (int i = 0; i < NLAYERS; i++) {
            k_gemm_tf32<0, 0, 0, 0><<<dim3(FDIM / 128, MT), 256, SM_T0, st>>>(
                NN_NODE, FDIM, FDIM, hin, lda, wrB + (size_t)i * FDIM * FDIM, FDIM,
                h1B, FDIM, nullptr);
            k_aggregate<<<NN_NODE, 64, 0, st>>>(h1B, b, bias + (size_t)i * FDIM, i);
            hin = featsB + (size_t)i * FDIM;
            lda = KTOT;
        }

        k_attfc<<<1, 32, 0, st>>>(fc1w, fc1b, fc2w, fc2b, b);
        k_weff<<<(OC * KTOT + 255) / 256, 256, 0, st>>>(cw, b);

        k_gemm_tf32<1, 1, 1, 0><<<dim3(1, MT), 256, SM_T1, st>>>(
            NN_NODE, OC, KTOT, featsB, KTOT,
            p_weff + (size_t)b * OC * KTOT, KTOT,
            p_emb + (size_t)b * NN_NODE * OC, OC, cb);
    }

    cudaEventRecord(g_hx.ev_j0, g_hx.s0);
    cudaEventRecord(g_hx.ev_j1, g_hx.s1);
    cudaStreamWaitEvent(0, g_hx.ev_j0, 0);
    cudaStreamWaitEvent(0, g_hx.ev_j1, 0);

    k_gemm_tf32<1, 0, 0, 1><<<dim3(MT, MT), 256, SM_T1>>>(
        NN_NODE, NN_NODE, OC,
        p_emb, OC,
        p_emb + (size_t)NN_NODE * OC, OC,
        out, NN_NODE, nullptr);
}

// round 6
// speedup vs baseline: 4.9777x; 1.3918x over previous
#include <cuda_runtime.h>
#include <cuda_fp16.h>
#include <math.h>
#include <stdint.h>

#define NN_NODE 10000
#define E_NUM   320000
#define FDIM    256
#define NLAYERS 5
#define OC      128
#define KTOT    (NLAYERS*FDIM)   // 1280

// ---------------- scratch ----------------
__device__ float g_dinv[2][NN_NODE];
__device__ int   g_cnt[2][NN_NODE];
__device__ int   g_rowptr[2][NN_NODE + 1];
__device__ int   g_csr_src[2][E_NUM];
__device__ float g_csr_norm[2][E_NUM];
__device__ __align__(16) __half g_feats[2][(size_t)NN_NODE * KTOT];     // fp16 activations
__device__ __align__(16) float  g_h1[2][(size_t)NN_NODE * FDIM];        // f32 pre-agg
__device__ __align__(16) __half g_xh[2][(size_t)NN_NODE * FDIM];        // fp16 inputs
__device__ __align__(16) __half g_wt[2][(size_t)NLAYERS * FDIM * FDIM]; // fp16 W^T
__device__ float g_amax[2][NLAYERS];
__device__ float g_atts[2][NLAYERS];
__device__ __align__(16) __half g_weff[2][OC * KTOT];
__device__ __align__(16) __half g_emb[2][(size_t)NN_NODE * OC];

// ---------------- FP16 cp.async GEMM 128x128x32, 3-stage ----------------
// C = A @ B^T.  A [M,K] half rm, B [N,K] half rm. K multiple of 32.
#define MMA_F16(d, a, b) \
  asm volatile("mma.sync.aligned.m16n8k16.row.col.f32.f16.f16.f32 " \
      "{%0,%1,%2,%3}, {%4,%5,%6,%7}, {%8,%9}, {%0,%1,%2,%3};" \
      : "+f"(d[0]), "+f"(d[1]), "+f"(d[2]), "+f"(d[3]) \
      : "r"(a[0]), "r"(a[1]), "r"(a[2]), "r"(a[3]), "r"(b[0]), "r"(b[1]))

__device__ __forceinline__ void cp16(uint32_t d, const void* s, bool p) {
    int sz = p ? 16 : 0;
    asm volatile("cp.async.cg.shared.global [%0], [%1], 16, %2;\n" :: "r"(d), "l"(s), "r"(sz));
}
__device__ __forceinline__ void cp_commit() { asm volatile("cp.async.commit_group;\n"); }
template <int N> __device__ __forceinline__ void cp_wait() {
    asm volatile("cp.async.wait_group %0;\n" :: "n"(N));
}

template <int BIAS, int OUT_HALF, int STREAM_OUT>
__global__ __launch_bounds__(256) void k_gemm_f16(
        int M, int N, int K,
        const __half* __restrict__ A, int lda,
        const __half* __restrict__ B, int ldb,
        void* __restrict__ Cv, int ldc,
        const float* __restrict__ bias) {
    constexpr int STAGES = 3;
    constexpr int LD32 = 20;            // 32 halves + 8 pad = 40 halves = 20 u32
    constexpr int A_ST = 128 * LD32;
    constexpr int B_ST = 128 * LD32;
    extern __shared__ uint32_t smem[];
    uint32_t* As = smem;
    uint32_t* Bs = smem + STAGES * A_ST;

    const int tid = threadIdx.x;
    const int wid = tid >> 5;
    const int lane = tid & 31;
    const int g = lane >> 2, t = lane & 3;
    const int wm = wid >> 1, wn = wid & 1;
    const int i0 = blockIdx.y * 128, j0 = blockIdx.x * 128;

    const int ar = tid >> 1, akc = (tid & 1) * 16;   // row, half-offset

    const bool a_ok = (i0 + ar < M);
    const __half* a_src = A + (size_t)(a_ok ? i0 + ar : M - 1) * lda + akc;
    const bool b_ok = (j0 + ar < N);
    const __half* b_src = B + (size_t)(b_ok ? j0 + ar : N - 1) * ldb + akc;

    uint32_t sa_base = (uint32_t)__cvta_generic_to_shared(&As[ar * LD32 + akc / 2]);
    uint32_t sb_base = (uint32_t)__cvta_generic_to_shared(&Bs[ar * LD32 + akc / 2]);

    auto issue = [&](int s, int k0) {
        uint32_t da = sa_base + s * (A_ST * 4);
        const __half* pa = a_src + k0;
        cp16(da,      pa,     a_ok);
        cp16(da + 16, pa + 8, a_ok);
        uint32_t db = sb_base + s * (B_ST * 4);
        const __half* pb = b_src + k0;
        cp16(db,      pb,     b_ok);
        cp16(db + 16, pb + 8, b_ok);
        cp_commit();
    };

    float acc[2][8][4];
    #pragma unroll
    for (int mt = 0; mt < 2; mt++)
        #pragma unroll
        for (int nt = 0; nt < 8; nt++)
            #pragma unroll
            for (int q = 0; q < 4; q++) acc[mt][nt][q] = 0.0f;

    auto compute = [&](int s) {
        const uint32_t* Ab = As + s * A_ST;
        const uint32_t* Bb = Bs + s * B_ST;
        #pragma unroll
        for (int c = 0; c < 2; c++) {          // two k16 chunks of the k32 tile
            const int base = c * 8;
            uint32_t af[2][4];
            #pragma unroll
            for (int mt = 0; mt < 2; mt++) {
                int r = wm * 32 + mt * 16;
                af[mt][0] = Ab[(r + g) * LD32 + base + t];
                af[mt][1] = Ab[(r + g + 8) * LD32 + base + t];
                af[mt][2] = Ab[(r + g) * LD32 + base + t + 4];
                af[mt][3] = Ab[(r + g + 8) * LD32 + base + t + 4];
            }
            uint32_t bf[8][2];
            #pragma unroll
            for (int nt = 0; nt < 8; nt++) {
                int n = wn * 64 + nt * 8 + g;
                bf[nt][0] = Bb[n * LD32 + base + t];
                bf[nt][1] = Bb[n * LD32 + base + t + 4];
            }
            #pragma unroll
            for (int mt = 0; mt < 2; mt++)
                #pragma unroll
                for (int nt = 0; nt < 8; nt++)
                    MMA_F16(acc[mt][nt], af[mt], bf[nt]);
        }
    };

    const int ktiles = K / 32;
    issue(0, 0);
    if (ktiles > 1) issue(1, 32);
    for (int i = 0; i < ktiles; i++) {
        // committed = min(i+2, ktiles); compute(i) needs group i done.
        // Last iteration: committed == i+1 -> must drain fully (R4 lesson).
        if (i < ktiles - 1) cp_wait<STAGES - 2>(); else cp_wait<0>();
        __syncthreads();
        int pf = i + STAGES - 1;
        if (pf < ktiles) issue(pf % STAGES, pf * 32);
        compute(i % STAGES);
    }

    #pragma unroll
    for (int mt = 0; mt < 2; mt++) {
        int r0 = i0 + wm * 32 + mt * 16 + g;
        #pragma unroll
        for (int nt = 0; nt < 8; nt++) {
            int c = j0 + wn * 64 + nt * 8 + 2 * t;
            if (c >= N) continue;
            float bx0 = 0.f, bx1 = 0.f;
            if (BIAS) { bx0 = bias[c]; bx1 = bias[c + 1]; }
            float v00 = acc[mt][nt][0] + bx0, v01 = acc[mt][nt][1] + bx1;
            float v10 = acc[mt][nt][2] + bx0, v11 = acc[mt][nt][3] + bx1;
            if (OUT_HALF) {
                __half* Ch = (__half*)Cv;
                __half2 h0 = __float22half2_rn(make_float2(v00, v01));
                __half2 h1 = __float22half2_rn(make_float2(v10, v11));
                if (r0 < M)     *(__half2*)(Ch + (size_t)r0 * ldc + c) = h0;
                if (r0 + 8 < M) *(__half2*)(Ch + (size_t)(r0 + 8) * ldc + c) = h1;
            } else {
                float* Cf = (float*)Cv;
                float2 p0 = make_float2(v00, v01);
                float2 p1 = make_float2(v10, v11);
                if (STREAM_OUT) {
                    if (r0 < M)     __stcs((float2*)(Cf + (size_t)r0 * ldc + c), p0);
                    if (r0 + 8 < M) __stcs((float2*)(Cf + (size_t)(r0 + 8) * ldc + c), p1);
                } else {
                    if (r0 < M)     *(float2*)(Cf + (size_t)r0 * ldc + c) = p0;
                    if (r0 + 8 < M) *(float2*)(Cf + (size_t)(r0 + 8) * ldc + c) = p1;
                }
            }
        }
    }
}

// ---------------- streams/events/attrs created once ----------------
struct HxRes {
    cudaStream_t s0, s1;
    cudaEvent_t ev_fork, ev_j0, ev_j1;
    HxRes() {
        cudaStreamCreateWithFlags(&s0, cudaStreamNonBlocking);
        cudaStreamCreateWithFlags(&s1, cudaStreamNonBlocking);
        cudaEventCreateWithFlags(&ev_fork, cudaEventDisableTiming);
        cudaEventCreateWithFlags(&ev_j0, cudaEventDisableTiming);
        cudaEventCreateWithFlags(&ev_j1, cudaEventDisableTiming);
        cudaFuncSetAttribute((const void*)k_gemm_f16<0,0,0>, cudaFuncAttributeMaxDynamicSharedMemorySize, 65536);
        cudaFuncSetAttribute((const void*)k_gemm_f16<1,1,0>, cudaFuncAttributeMaxDynamicSharedMemorySize, 65536);
        cudaFuncSetAttribute((const void*)k_gemm_f16<0,0,1>, cudaFuncAttributeMaxDynamicSharedMemorySize, 65536);
    }
};
static HxRes g_hx;

// ---------------- prep kernels ----------------
__global__ void k_init() {
    int i = blockIdx.x * blockDim.x + threadIdx.x;
    if (i < NN_NODE) {
        g_dinv[0][i] = 1.0f; g_dinv[1][i] = 1.0f;
        g_cnt[0][i] = 0;     g_cnt[1][i] = 0;
    }
    if (i < NLAYERS) { g_amax[0][i] = 0.0f; g_amax[1][i] = 0.0f; }
}

// float -> half (vectorized)
__global__ void k_halfcpy(const float* __restrict__ in, __half* __restrict__ out, int n4) {
    int i = blockIdx.x * blockDim.x + threadIdx.x;
    if (i < n4) {
        float4 v = ((const float4*)in)[i];
        __half2 h0 = __float22half2_rn(make_float2(v.x, v.y));
        __half2 h1 = __float22half2_rn(make_float2(v.z, v.w));
        ((uint2*)out)[i] = make_uint2(*(uint32_t*)&h0, *(uint32_t*)&h1);
    }
}

// W [L][K][N] f32 -> W^T [L][N][K] half
__global__ void k_halfT(const float* __restrict__ in, __half* __restrict__ out, int total) {
    int idx = blockIdx.x * blockDim.x + threadIdx.x;
    if (idx < total) {
        int l = idx >> 16;            // /65536
        int rem = idx & 65535;
        int k = rem >> 8, n = rem & 255;
        out[(size_t)l * 65536 + n * 256 + k] = __float2half(in[idx]);
    }
}

__global__ void k_deg_cnt(const int* __restrict__ edges, const float* __restrict__ w, int b) {
    int e = blockIdx.x * blockDim.x + threadIdx.x;
    if (e < E_NUM) {
        int dst = edges[E_NUM + e];
        atomicAdd(&g_dinv[b][dst], w[e]);
        atomicAdd(&g_cnt[b][dst], 1);
    }
}

__global__ void k_rsqrt(int b) {
    int i = blockIdx.x * blockDim.x + threadIdx.x;
    if (i < NN_NODE) g_dinv[b][i] = rsqrtf(g_dinv[b][i]);
}

__global__ void k_scan(int b) {
    __shared__ int wsum[32];
    __shared__ int chunk_base;
    int tid = threadIdx.x, lane = tid & 31, w = tid >> 5;
    if (tid == 0) chunk_base = 0;
    __syncthreads();
    for (int c0 = 0; c0 < NN_NODE; c0 += 1024) {
        int idx = c0 + tid;
        int v = (idx < NN_NODE) ? g_cnt[b][idx] : 0;
        int sc = v;
        #pragma unroll
        for (int off = 1; off < 32; off <<= 1) {
            int u = __shfl_up_sync(0xffffffffu, sc, off);
            if (lane >= off) sc += u;
        }
        if (lane == 31) wsum[w] = sc;
        __syncthreads();
        if (w == 0) {
            int tv = wsum[lane];
            #pragma unroll
            for (int off = 1; off < 32; off <<= 1) {
                int u = __shfl_up_sync(0xffffffffu, tv, off);
                if (lane >= off) tv += u;
            }
            wsum[lane] = tv;
        }
        __syncthreads();
        int total = wsum[31];
        int excl = chunk_base + (w ? wsum[w - 1] : 0) + sc - v;
        if (idx < NN_NODE) { g_rowptr[b][idx] = excl; g_cnt[b][idx] = 0; }
        __syncthreads();
        if (tid == 0) chunk_base += total;
        __syncthreads();
    }
    if (tid == 0) g_rowptr[b][NN_NODE] = chunk_base;
}

__global__ void k_fill(const int* __restrict__ edges, const float* __restrict__ w, int b) {
    int e = blockIdx.x * blockDim.x + threadIdx.x;
    if (e < E_NUM) {
        int s = edges[e];
        int d = edges[E_NUM + e];
        int pos = g_rowptr[b][d] + atomicAdd(&g_cnt[b][d], 1);
        g_csr_src[b][pos] = s;
        g_csr_norm[b][pos] = g_dinv[b][s] * w[e] * g_dinv[b][d];
    }
}

// ---------------- aggregation (float4 gather, fused max pool, half output) ----------------
__global__ __launch_bounds__(64) void k_aggregate(const float* __restrict__ h1, int b,
                                                  const float* __restrict__ bias, int layer) {
    __shared__ float red2[2];
    int v = blockIdx.x;
    int t = threadIdx.x;                 // 0..63 (float4 lane)
    const float4* h1v = (const float4*)h1;
    float dv = g_dinv[b][v];
    float sw = dv * dv;
    float4 a = h1v[(size_t)v * 64 + t];
    float4 acc = make_float4(sw * a.x, sw * a.y, sw * a.z, sw * a.w);
    int e = g_rowptr[b][v];
    int e2 = g_rowptr[b][v + 1];
    const int*   srcs  = g_csr_src[b];
    const float* norms = g_csr_norm[b];
    for (; e + 4 <= e2; e += 4) {
        int u0 = srcs[e], u1 = srcs[e + 1], u2 = srcs[e + 2], u3 = srcs[e + 3];
        float n0 = norms[e], n1 = norms[e + 1], n2 = norms[e + 2], n3 = norms[e + 3];
        float4 x0 = h1v[(size_t)u0 * 64 + t];
        float4 x1 = h1v[(size_t)u1 * 64 + t];
        float4 x2 = h1v[(size_t)u2 * 64 + t];
        float4 x3 = h1v[(size_t)u3 * 64 + t];
        acc.x += n0 * x0.x + n1 * x1.x + n2 * x2.x + n3 * x3.x;
        acc.y += n0 * x0.y + n1 * x1.y + n2 * x2.y + n3 * x3.y;
        acc.z += n0 * x0.z + n1 * x1.z + n2 * x2.z + n3 * x3.z;
        acc.w += n0 * x0.w + n1 * x1.w + n2 * x2.w + n3 * x3.w;
    }
    for (; e < e2; e++) {
        float n = norms[e];
        float4 x = h1v[(size_t)srcs[e] * 64 + t];
        acc.x += n * x.x; acc.y += n * x.y; acc.z += n * x.z; acc.w += n * x.w;
    }
    float4 bv = ((const float4*)bias)[t];
    acc.x = fmaxf(acc.x + bv.x, 0.f);
    acc.y = fmaxf(acc.y + bv.y, 0.f);
    acc.z = fmaxf(acc.z + bv.z, 0.f);
    acc.w = fmaxf(acc.w + bv.w, 0.f);
    __half2 h0 = __float22half2_rn(make_float2(acc.x, acc.y));
    __half2 h1p = __float22half2_rn(make_float2(acc.z, acc.w));
    *(uint2*)&g_feats[b][(size_t)v * KTOT + layer * FDIM + t * 4] =
        make_uint2(*(uint32_t*)&h0, *(uint32_t*)&h1p);

    float m = fmaxf(fmaxf(acc.x, acc.y), fmaxf(acc.z, acc.w));
    #pragma unroll
    for (int off = 16; off > 0; off >>= 1)
        m = fmaxf(m, __shfl_xor_sync(0xffffffffu, m, off));
    if ((t & 31) == 0) red2[t >> 5] = m;
    __syncthreads();
    if (t == 0)
        atomicMax((int*)&g_amax[b][layer], __float_as_int(fmaxf(red2[0], red2[1])));
}

// ---------------- attention FC + effective conv weights ----------------
__global__ void k_attfc(const float* __restrict__ fc1w, const float* __restrict__ fc1b,
                        const float* __restrict__ fc2w, const float* __restrict__ fc2b, int b) {
    if (threadIdx.x == 0 && blockIdx.x == 0) {
        float a[NLAYERS];
        for (int c = 0; c < NLAYERS; c++) a[c] = g_amax[b][c];
        float t[5 * NLAYERS];
        for (int j = 0; j < 5 * NLAYERS; j++) {
            float s = fc1b[j];
            for (int c = 0; c < NLAYERS; c++) s += fc1w[j * NLAYERS + c] * a[c];
            t[j] = fmaxf(s, 0.f);
        }
        for (int c = 0; c < NLAYERS; c++) {
            float s = fc2b[c];
            for (int j = 0; j < 5 * NLAYERS; j++) s += fc2w[c * (5 * NLAYERS) + j] * t[j];
            g_atts[b][c] = 1.0f / (1.0f + expf(-s));
        }
    }
}

__global__ void k_weff(const float* __restrict__ cw, int b) {
    int idx = blockIdx.x * blockDim.x + threadIdx.x;
    if (idx < OC * KTOT) {
        int c = (idx % KTOT) >> 8;
        g_weff[b][idx] = __float2half(cw[idx] * g_atts[b][c]);
    }
}

// ---------------- launch ----------------
extern "C" void kernel_launch(void* const* d_in, const int* in_sizes, int n_in,
                              void* d_out, int out_size) {
    const float* x_m    = (const float*)d_in[0];
    const float* x_d    = (const float*)d_in[1];
    const float* w_m    = (const float*)d_in[2];
    const float* w_d    = (const float*)d_in[3];
    const float* Wx     = (const float*)d_in[4];
    const float* bx     = (const float*)d_in[5];
    const float* Wy     = (const float*)d_in[6];
    const float* by     = (const float*)d_in[7];
    const float* fc1x_w = (const float*)d_in[8];
    const float* fc1x_b = (const float*)d_in[9];
    const float* fc2x_w = (const float*)d_in[10];
    const float* fc2x_b = (const float*)d_in[11];
    const float* fc1y_w = (const float*)d_in[12];
    const float* fc1y_b = (const float*)d_in[13];
    const float* fc2y_w = (const float*)d_in[14];
    const float* fc2y_b = (const float*)d_in[15];
    const float* cnnx_w = (const float*)d_in[16];
    const float* cnnx_b = (const float*)d_in[17];
    const float* cnny_w = (const float*)d_in[18];
    const float* cnny_b = (const float*)d_in[19];
    const int*   edges_m = (const int*)d_in[20];
    const int*   edges_d = (const int*)d_in[21];
    float* out = (float*)d_out;

    float *p_h1;
    __half *p_feats, *p_weff, *p_emb, *p_xh, *p_wt;
    cudaGetSymbolAddress((void**)&p_h1,    g_h1);
    cudaGetSymbolAddress((void**)&p_feats, g_feats);
    cudaGetSymbolAddress((void**)&p_weff,  g_weff);
    cudaGetSymbolAddress((void**)&p_emb,   g_emb);
    cudaGetSymbolAddress((void**)&p_xh,    g_xh);
    cudaGetSymbolAddress((void**)&p_wt,    g_wt);

    const int MT = (NN_NODE + 127) / 128;   // 79
    const int SM_F16 = 3 * (128 * 20 + 128 * 20) * 4;  // 61440

    k_init<<<(NN_NODE + 255) / 256, 256>>>();
    cudaEventRecord(g_hx.ev_fork, 0);
    cudaStreamWaitEvent(g_hx.s0, g_hx.ev_fork, 0);
    cudaStreamWaitEvent(g_hx.s1, g_hx.ev_fork, 0);

    for (int b = 0; b < 2; b++) {
        cudaStream_t st = b ? g_hx.s1 : g_hx.s0;
        const int*   edges = b ? edges_d : edges_m;
        const float* w     = b ? w_d : w_m;
        const float* W     = b ? Wy : Wx;
        const float* bias  = b ? by : bx;
        const float* fc1w  = b ? fc1y_w : fc1x_w;
        const float* fc1b  = b ? fc1y_b : fc1x_b;
        const float* fc2w  = b ? fc2y_w : fc2x_w;
        const float* fc2b  = b ? fc2y_b : fc2x_b;
        const float* cw    = b ? cnny_w : cnnx_w;
        const float* cb    = b ? cnny_b : cnnx_b;
        const float* x0    = b ? x_d : x_m;
        __half* featsB = p_feats + (size_t)b * NN_NODE * KTOT;
        float*  h1B    = p_h1    + (size_t)b * NN_NODE * FDIM;
        __half* xhB    = p_xh    + (size_t)b * NN_NODE * FDIM;
        __half* wtB    = p_wt    + (size_t)b * NLAYERS * FDIM * FDIM;

        k_halfcpy<<<(NN_NODE * FDIM / 4 + 255) / 256, 256, 0, st>>>(x0, xhB, NN_NODE * FDIM / 4);
        k_halfT<<<(NLAYERS * FDIM * FDIM + 255) / 256, 256, 0, st>>>(W, wtB, NLAYERS * FDIM * FDIM);

        k_deg_cnt<<<E_NUM / 256, 256, 0, st>>>(edges, w, b);
        k_rsqrt<<<(NN_NODE + 255) / 256, 256, 0, st>>>(b);
        k_scan<<<1, 1024, 0, st>>>(b);
        k_fill<<<E_NUM / 256, 256, 0, st>>>(edges, w, b);

        const __half* hin = xhB;
        int lda = FDIM;
        for (int i = 0; i < NLAYERS; i++) {
            k_gemm_f16<0, 0, 0><<<dim3(FDIM / 128, MT), 256, SM_F16, st>>>(
                NN_NODE, FDIM, FDIM, hin, lda, wtB + (size_t)i * FDIM * FDIM, FDIM,
                h1B, FDIM, nullptr);
            k_aggregate<<<NN_NODE, 64, 0, st>>>(h1B, b, bias + (size_t)i * FDIM, i);
            hin = featsB + (size_t)i * FDIM;
            lda = KTOT;
        }

        k_attfc<<<1, 32, 0, st>>>(fc1w, fc1b, fc2w, fc2b, b);
        k_weff<<<(OC * KTOT + 255) / 256, 256, 0, st>>>(cw, b);

        k_gemm_f16<1, 1, 0><<<dim3(1, MT), 256, SM_F16, st>>>(
            NN_NODE, OC, KTOT, featsB, KTOT,
            p_weff + (size_t)b * OC * KTOT, KTOT,
            p_emb + (size_t)b * NN_NODE * OC, OC, cb);
    }

    cudaEventRecord(g_hx.ev_j0, g_hx.s0);
    cudaEventRecord(g_hx.ev_j1, g_hx.s1);
    cudaStreamWaitEvent(0, g_hx.ev_j0, 0);
    cudaStreamWaitEvent(0, g_hx.ev_j1, 0);

    k_gemm_f16<0, 0, 1><<<dim3(MT, MT), 256, SM_F16>>>(
        NN_NODE, NN_NODE, OC,
        p_emb, OC,
        p_emb + (size_t)NN_NODE * OC, OC,
        out, NN_NODE, nullptr);
}

// round 7
// speedup vs baseline: 5.1682x; 1.0383x over previous
#include <cuda_runtime.h>
#include <cuda_fp16.h>
#include <math.h>
#include <stdint.h>

#define NN_NODE 10000
#define E_NUM   320000
#define FDIM    256
#define NLAYERS 5
#define OC      128
#define KTOT    (NLAYERS*FDIM)   // 1280

// ---------------- scratch ----------------
__device__ float g_dinv[2][NN_NODE];
__device__ int   g_cnt[2][NN_NODE];
__device__ int   g_rowptr[2][NN_NODE + 1];
__device__ int   g_csr_src[2][E_NUM];
__device__ float g_csr_norm[2][E_NUM];
__device__ __align__(16) __half g_feats[2][(size_t)NN_NODE * KTOT];     // fp16 activations
__device__ __align__(16) __half g_h1[2][(size_t)NN_NODE * FDIM];        // fp16 pre-agg
__device__ __align__(16) __half g_xh[2][(size_t)NN_NODE * FDIM];        // fp16 inputs
__device__ __align__(16) __half g_wt[2][(size_t)NLAYERS * FDIM * FDIM]; // fp16 W^T
__device__ float g_amax[2][NLAYERS];
__device__ float g_atts[2][NLAYERS];
__device__ __align__(16) __half g_weff[2][OC * KTOT];
__device__ __align__(16) __half g_emb[2][(size_t)NN_NODE * OC];

// ---------------- FP16 cp.async GEMM 128x128x32, 3-stage ----------------
// C = A @ B^T.  A [M,K] half rm, B [N,K] half rm. K multiple of 32.
#define MMA_F16(d, a, b) \
  asm volatile("mma.sync.aligned.m16n8k16.row.col.f32.f16.f16.f32 " \
      "{%0,%1,%2,%3}, {%4,%5,%6,%7}, {%8,%9}, {%0,%1,%2,%3};" \
      : "+f"(d[0]), "+f"(d[1]), "+f"(d[2]), "+f"(d[3]) \
      : "r"(a[0]), "r"(a[1]), "r"(a[2]), "r"(a[3]), "r"(b[0]), "r"(b[1]))

__device__ __forceinline__ void cp16(uint32_t d, const void* s, bool p) {
    int sz = p ? 16 : 0;
    asm volatile("cp.async.cg.shared.global [%0], [%1], 16, %2;\n" :: "r"(d), "l"(s), "r"(sz));
}
__device__ __forceinline__ void cp_commit() { asm volatile("cp.async.commit_group;\n"); }
template <int N> __device__ __forceinline__ void cp_wait() {
    asm volatile("cp.async.wait_group %0;\n" :: "n"(N));
}

template <int BIAS, int OUT_HALF, int STREAM_OUT>
__global__ __launch_bounds__(256) void k_gemm_f16(
        int M, int N, int K,
        const __half* __restrict__ A, int lda,
        const __half* __restrict__ B, int ldb,
        void* __restrict__ Cv, int ldc,
        const float* __restrict__ bias) {
    constexpr int STAGES = 3;
    constexpr int LD32 = 20;            // 32 halves + 8 pad = 40 halves = 20 u32
    constexpr int A_ST = 128 * LD32;
    constexpr int B_ST = 128 * LD32;
    extern __shared__ uint32_t smem[];
    uint32_t* As = smem;
    uint32_t* Bs = smem + STAGES * A_ST;

    const int tid = threadIdx.x;
    const int wid = tid >> 5;
    const int lane = tid & 31;
    const int g = lane >> 2, t = lane & 3;
    const int wm = wid >> 1, wn = wid & 1;
    const int i0 = blockIdx.y * 128, j0 = blockIdx.x * 128;

    const int ar = tid >> 1, akc = (tid & 1) * 16;   // row, half-offset

    const bool a_ok = (i0 + ar < M);
    const __half* a_src = A + (size_t)(a_ok ? i0 + ar : M - 1) * lda + akc;
    const bool b_ok = (j0 + ar < N);
    const __half* b_src = B + (size_t)(b_ok ? j0 + ar : N - 1) * ldb + akc;

    uint32_t sa_base = (uint32_t)__cvta_generic_to_shared(&As[ar * LD32 + akc / 2]);
    uint32_t sb_base = (uint32_t)__cvta_generic_to_shared(&Bs[ar * LD32 + akc / 2]);

    auto issue = [&](int s, int k0) {
        uint32_t da = sa_base + s * (A_ST * 4);
        const __half* pa = a_src + k0;
        cp16(da,      pa,     a_ok);
        cp16(da + 16, pa + 8, a_ok);
        uint32_t db = sb_base + s * (B_ST * 4);
        const __half* pb = b_src + k0;
        cp16(db,      pb,     b_ok);
        cp16(db + 16, pb + 8, b_ok);
        cp_commit();
    };

    float acc[2][8][4];
    #pragma unroll
    for (int mt = 0; mt < 2; mt++)
        #pragma unroll
        for (int nt = 0; nt < 8; nt++)
            #pragma unroll
            for (int q = 0; q < 4; q++) acc[mt][nt][q] = 0.0f;

    auto compute = [&](int s) {
        const uint32_t* Ab = As + s * A_ST;
        const uint32_t* Bb = Bs + s * B_ST;
        #pragma unroll
        for (int c = 0; c < 2; c++) {          // two k16 chunks of the k32 tile
            const int base = c * 8;
            uint32_t af[2][4];
            #pragma unroll
            for (int mt = 0; mt < 2; mt++) {
                int r = wm * 32 + mt * 16;
                af[mt][0] = Ab[(r + g) * LD32 + base + t];
                af[mt][1] = Ab[(r + g + 8) * LD32 + base + t];
                af[mt][2] = Ab[(r + g) * LD32 + base + t + 4];
                af[mt][3] = Ab[(r + g + 8) * LD32 + base + t + 4];
            }
            uint32_t bf[8][2];
            #pragma unroll
            for (int nt = 0; nt < 8; nt++) {
                int n = wn * 64 + nt * 8 + g;
                bf[nt][0] = Bb[n * LD32 + base + t];
                bf[nt][1] = Bb[n * LD32 + base + t + 4];
            }
            #pragma unroll
            for (int mt = 0; mt < 2; mt++)
                #pragma unroll
                for (int nt = 0; nt < 8; nt++)
                    MMA_F16(acc[mt][nt], af[mt], bf[nt]);
        }
    };

    const int ktiles = K / 32;
    issue(0, 0);
    if (ktiles > 1) issue(1, 32);
    for (int i = 0; i < ktiles; i++) {
        // committed = min(i+2, ktiles); compute(i) needs group i done.
        // Last iteration: committed == i+1 -> must drain fully.
        if (i < ktiles - 1) cp_wait<STAGES - 2>(); else cp_wait<0>();
        __syncthreads();
        int pf = i + STAGES - 1;
        if (pf < ktiles) issue(pf % STAGES, pf * 32);
        compute(i % STAGES);
    }

    #pragma unroll
    for (int mt = 0; mt < 2; mt++) {
        int r0 = i0 + wm * 32 + mt * 16 + g;
        #pragma unroll
        for (int nt = 0; nt < 8; nt++) {
            int c = j0 + wn * 64 + nt * 8 + 2 * t;
            if (c >= N) continue;
            float bx0 = 0.f, bx1 = 0.f;
            if (BIAS) { bx0 = bias[c]; bx1 = bias[c + 1]; }
            float v00 = acc[mt][nt][0] + bx0, v01 = acc[mt][nt][1] + bx1;
            float v10 = acc[mt][nt][2] + bx0, v11 = acc[mt][nt][3] + bx1;
            if (OUT_HALF) {
                __half* Ch = (__half*)Cv;
                __half2 h0 = __float22half2_rn(make_float2(v00, v01));
                __half2 h1 = __float22half2_rn(make_float2(v10, v11));
                if (r0 < M)     *(__half2*)(Ch + (size_t)r0 * ldc + c) = h0;
                if (r0 + 8 < M) *(__half2*)(Ch + (size_t)(r0 + 8) * ldc + c) = h1;
            } else {
                float* Cf = (float*)Cv;
                float2 p0 = make_float2(v00, v01);
                float2 p1 = make_float2(v10, v11);
                if (STREAM_OUT) {
                    if (r0 < M)     __stcs((float2*)(Cf + (size_t)r0 * ldc + c), p0);
                    if (r0 + 8 < M) __stcs((float2*)(Cf + (size_t)(r0 + 8) * ldc + c), p1);
                } else {
                    if (r0 < M)     *(float2*)(Cf + (size_t)r0 * ldc + c) = p0;
                    if (r0 + 8 < M) *(float2*)(Cf + (size_t)(r0 + 8) * ldc + c) = p1;
                }
            }
        }
    }
}

// ---------------- streams/events/attrs created once ----------------
struct HxRes {
    cudaStream_t s0, s1;
    cudaEvent_t ev_fork, ev_j0, ev_j1;
    HxRes() {
        cudaStreamCreateWithFlags(&s0, cudaStreamNonBlocking);
        cudaStreamCreateWithFlags(&s1, cudaStreamNonBlocking);
        cudaEventCreateWithFlags(&ev_fork, cudaEventDisableTiming);
        cudaEventCreateWithFlags(&ev_j0, cudaEventDisableTiming);
        cudaEventCreateWithFlags(&ev_j1, cudaEventDisableTiming);
        cudaFuncSetAttribute((const void*)k_gemm_f16<0,1,0>, cudaFuncAttributeMaxDynamicSharedMemorySize, 65536);
        cudaFuncSetAttribute((const void*)k_gemm_f16<1,1,0>, cudaFuncAttributeMaxDynamicSharedMemorySize, 65536);
        cudaFuncSetAttribute((const void*)k_gemm_f16<0,0,1>, cudaFuncAttributeMaxDynamicSharedMemorySize, 65536);
    }
};
static HxRes g_hx;

// ---------------- prep kernels ----------------
__global__ void k_init() {
    int i = blockIdx.x * blockDim.x + threadIdx.x;
    if (i < NN_NODE) {
        g_dinv[0][i] = 1.0f; g_dinv[1][i] = 1.0f;
        g_cnt[0][i] = 0;     g_cnt[1][i] = 0;
    }
    if (i < NLAYERS) { g_amax[0][i] = 0.0f; g_amax[1][i] = 0.0f; }
}

// float -> half (vectorized)
__global__ void k_halfcpy(const float* __restrict__ in, __half* __restrict__ out, int n4) {
    int i = blockIdx.x * blockDim.x + threadIdx.x;
    if (i < n4) {
        float4 v = ((const float4*)in)[i];
        __half2 h0 = __float22half2_rn(make_float2(v.x, v.y));
        __half2 h1 = __float22half2_rn(make_float2(v.z, v.w));
        ((uint2*)out)[i] = make_uint2(*(uint32_t*)&h0, *(uint32_t*)&h1);
    }
}

// W [L][K][N] f32 -> W^T [L][N][K] half
__global__ void k_halfT(const float* __restrict__ in, __half* __restrict__ out, int total) {
    int idx = blockIdx.x * blockDim.x + threadIdx.x;
    if (idx < total) {
        int l = idx >> 16;
        int rem = idx & 65535;
        int k = rem >> 8, n = rem & 255;
        out[(size_t)l * 65536 + n * 256 + k] = __float2half(in[idx]);
    }
}

__global__ void k_deg_cnt(const int* __restrict__ edges, const float* __restrict__ w, int b) {
    int e = blockIdx.x * blockDim.x + threadIdx.x;
    if (e < E_NUM) {
        int dst = edges[E_NUM + e];
        atomicAdd(&g_dinv[b][dst], w[e]);
        atomicAdd(&g_cnt[b][dst], 1);
    }
}

// scan of g_cnt -> g_rowptr (resets g_cnt) + fused rsqrt(dinv)
__global__ void k_scan(int b) {
    __shared__ int wsum[32];
    __shared__ int chunk_base;
    int tid = threadIdx.x, lane = tid & 31, w = tid >> 5;
    if (tid == 0) chunk_base = 0;
    __syncthreads();
    for (int c0 = 0; c0 < NN_NODE; c0 += 1024) {
        int idx = c0 + tid;
        int v = (idx < NN_NODE) ? g_cnt[b][idx] : 0;
        if (idx < NN_NODE) g_dinv[b][idx] = rsqrtf(g_dinv[b][idx]);
        int sc = v;
        #pragma unroll
        for (int off = 1; off < 32; off <<= 1) {
            int u = __shfl_up_sync(0xffffffffu, sc, off);
            if (lane >= off) sc += u;
        }
        if (lane == 31) wsum[w] = sc;
        __syncthreads();
        if (w == 0) {
            int tv = wsum[lane];
            #pragma unroll
            for (int off = 1; off < 32; off <<= 1) {
                int u = __shfl_up_sync(0xffffffffu, tv, off);
                if (lane >= off) tv += u;
            }
            wsum[lane] = tv;
        }
        __syncthreads();
        int total = wsum[31];
        int excl = chunk_base + (w ? wsum[w - 1] : 0) + sc - v;
        if (idx < NN_NODE) { g_rowptr[b][idx] = excl; g_cnt[b][idx] = 0; }
        __syncthreads();
        if (tid == 0) chunk_base += total;
        __syncthreads();
    }
    if (tid == 0) g_rowptr[b][NN_NODE] = chunk_base;
}

__global__ void k_fill(const int* __restrict__ edges, const float* __restrict__ w, int b) {
    int e = blockIdx.x * blockDim.x + threadIdx.x;
    if (e < E_NUM) {
        int s = edges[e];
        int d = edges[E_NUM + e];
        int pos = g_rowptr[b][d] + atomicAdd(&g_cnt[b][d], 1);
        g_csr_src[b][pos] = s;
        g_csr_norm[b][pos] = g_dinv[b][s] * w[e] * g_dinv[b][d];
    }
}

// ---------------- aggregation (half gather, f32 accum, fused max pool) ----------------
__global__ __launch_bounds__(64) void k_aggregate(const __half* __restrict__ h1, int b,
                                                  const float* __restrict__ bias, int layer) {
    __shared__ float red2[2];
    int v = blockIdx.x;
    int t = threadIdx.x;                 // 0..63, 4 halves each
    const uint2* h1v = (const uint2*)h1; // 4 halves per uint2
    float dv = g_dinv[b][v];
    float sw = dv * dv;

    uint2 raw = h1v[(size_t)v * 64 + t];
    float2 a01 = __half22float2(*(__half2*)&raw.x);
    float2 a23 = __half22float2(*(__half2*)&raw.y);
    float4 acc = make_float4(sw * a01.x, sw * a01.y, sw * a23.x, sw * a23.y);

    int e = g_rowptr[b][v];
    int e2 = g_rowptr[b][v + 1];
    const int*   srcs  = g_csr_src[b];
    const float* norms = g_csr_norm[b];
    for (; e + 4 <= e2; e += 4) {
        int u0 = srcs[e], u1 = srcs[e + 1], u2 = srcs[e + 2], u3 = srcs[e + 3];
        float n0 = norms[e], n1 = norms[e + 1], n2 = norms[e + 2], n3 = norms[e + 3];
        uint2 r0 = h1v[(size_t)u0 * 64 + t];
        uint2 r1 = h1v[(size_t)u1 * 64 + t];
        uint2 r2 = h1v[(size_t)u2 * 64 + t];
        uint2 r3 = h1v[(size_t)u3 * 64 + t];
        float2 x0a = __half22float2(*(__half2*)&r0.x), x0b = __half22float2(*(__half2*)&r0.y);
        float2 x1a = __half22float2(*(__half2*)&r1.x), x1b = __half22float2(*(__half2*)&r1.y);
        float2 x2a = __half22float2(*(__half2*)&r2.x), x2b = __half22float2(*(__half2*)&r2.y);
        float2 x3a = __half22float2(*(__half2*)&r3.x), x3b = __half22float2(*(__half2*)&r3.y);
        acc.x += n0 * x0a.x + n1 * x1a.x + n2 * x2a.x + n3 * x3a.x;
        acc.y += n0 * x0a.y + n1 * x1a.y + n2 * x2a.y + n3 * x3a.y;
        acc.z += n0 * x0b.x + n1 * x1b.x + n2 * x2b.x + n3 * x3b.x;
        acc.w += n0 * x0b.y + n1 * x1b.y + n2 * x2b.y + n3 * x3b.y;
    }
    for (; e < e2; e++) {
        float n = norms[e];
        uint2 r = h1v[(size_t)srcs[e] * 64 + t];
        float2 xa = __half22float2(*(__half2*)&r.x), xb = __half22float2(*(__half2*)&r.y);
        acc.x += n * xa.x; acc.y += n * xa.y; acc.z += n * xb.x; acc.w += n * xb.y;
    }
    float4 bv = ((const float4*)bias)[t];
    acc.x = fmaxf(acc.x + bv.x, 0.f);
    acc.y = fmaxf(acc.y + bv.y, 0.f);
    acc.z = fmaxf(acc.z + bv.z, 0.f);
    acc.w = fmaxf(acc.w + bv.w, 0.f);
    __half2 h0 = __float22half2_rn(make_float2(acc.x, acc.y));
    __half2 h1p = __float22half2_rn(make_float2(acc.z, acc.w));
    *(uint2*)&g_feats[b][(size_t)v * KTOT + layer * FDIM + t * 4] =
        make_uint2(*(uint32_t*)&h0, *(uint32_t*)&h1p);

    float m = fmaxf(fmaxf(acc.x, acc.y), fmaxf(acc.z, acc.w));
    #pragma unroll
    for (int off = 16; off > 0; off >>= 1)
        m = fmaxf(m, __shfl_xor_sync(0xffffffffu, m, off));
    if ((t & 31) == 0) red2[t >> 5] = m;
    __syncthreads();
    if (t == 0)
        atomicMax((int*)&g_amax[b][layer], __float_as_int(fmaxf(red2[0], red2[1])));
}

// ---------------- attention FC + effective conv weights ----------------
__global__ void k_attfc(const float* __restrict__ fc1w, const float* __restrict__ fc1b,
                        const float* __restrict__ fc2w, const float* __restrict__ fc2b, int b) {
    if (threadIdx.x == 0 && blockIdx.x == 0) {
        float a[NLAYERS];
        for (int c = 0; c < NLAYERS; c++) a[c] = g_amax[b][c];
        float t[5 * NLAYERS];
        for (int j = 0; j < 5 * NLAYERS; j++) {
            float s = fc1b[j];
            for (int c = 0; c < NLAYERS; c++) s += fc1w[j * NLAYERS + c] * a[c];
            t[j] = fmaxf(s, 0.f);
        }
        for (int c = 0; c < NLAYERS; c++) {
            float s = fc2b[c];
            for (int j = 0; j < 5 * NLAYERS; j++) s += fc2w[c * (5 * NLAYERS) + j] * t[j];
            g_atts[b][c] = 1.0f / (1.0f + expf(-s));
        }
    }
}

__global__ void k_weff(const float* __restrict__ cw, int b) {
    int idx = blockIdx.x * blockDim.x + threadIdx.x;
    if (idx < OC * KTOT) {
        int c = (idx % KTOT) >> 8;
        g_weff[b][idx] = __float2half(cw[idx] * g_atts[b][c]);
    }
}

// ---------------- launch ----------------
extern "C" void kernel_launch(void* const* d_in, const int* in_sizes, int n_in,
                              void* d_out, int out_size) {
    const float* x_m    = (const float*)d_in[0];
    const float* x_d    = (const float*)d_in[1];
    const float* w_m    = (const float*)d_in[2];
    const float* w_d    = (const float*)d_in[3];
    const float* Wx     = (const float*)d_in[4];
    const float* bx     = (const float*)d_in[5];
    const float* Wy     = (const float*)d_in[6];
    const float* by     = (const float*)d_in[7];
    const float* fc1x_w = (const float*)d_in[8];
    const float* fc1x_b = (const float*)d_in[9];
    const float* fc2x_w = (const float*)d_in[10];
    const float* fc2x_b = (const float*)d_in[11];
    const float* fc1y_w = (const float*)d_in[12];
    const float* fc1y_b = (const float*)d_in[13];
    const float* fc2y_w = (const float*)d_in[14];
    const float* fc2y_b = (const float*)d_in[15];
    const float* cnnx_w = (const float*)d_in[16];
    const float* cnnx_b = (const float*)d_in[17];
    const float* cnny_w = (const float*)d_in[18];
    const float* cnny_b = (const float*)d_in[19];
    const int*   edges_m = (const int*)d_in[20];
    const int*   edges_d = (const int*)d_in[21];
    float* out = (float*)d_out;

    __half *p_h1, *p_feats, *p_weff, *p_emb, *p_xh, *p_wt;
    cudaGetSymbolAddress((void**)&p_h1,    g_h1);
    cudaGetSymbolAddress((void**)&p_feats, g_feats);
    cudaGetSymbolAddress((void**)&p_weff,  g_weff);
    cudaGetSymbolAddress((void**)&p_emb,   g_emb);
    cudaGetSymbolAddress((void**)&p_xh,    g_xh);
    cudaGetSymbolAddress((void**)&p_wt,    g_wt);

    const int MT = (NN_NODE + 127) / 128;   // 79
    const int SM_F16 = 3 * (128 * 20 + 128 * 20) * 4;  // 61440

    k_init<<<(NN_NODE + 255) / 256, 256>>>();
    cudaEventRecord(g_hx.ev_fork, 0);
    cudaStreamWaitEvent(g_hx.s0, g_hx.ev_fork, 0);
    cudaStreamWaitEvent(g_hx.s1, g_hx.ev_fork, 0);

    for (int b = 0; b < 2; b++) {
        cudaStream_t st = b ? g_hx.s1 : g_hx.s0;
        const int*   edges = b ? edges_d : edges_m;
        const float* w     = b ? w_d : w_m;
        const float* W     = b ? Wy : Wx;
        const float* bias  = b ? by : bx;
        const float* fc1w  = b ? fc1y_w : fc1x_w;
        const float* fc1b  = b ? fc1y_b : fc1x_b;
        const float* fc2w  = b ? fc2y_w : fc2x_w;
        const float* fc2b  = b ? fc2y_b : fc2x_b;
        const float* cw    = b ? cnny_w : cnnx_w;
        const float* cb    = b ? cnny_b : cnnx_b;
        const float* x0    = b ? x_d : x_m;
        __half* featsB = p_feats + (size_t)b * NN_NODE * KTOT;
        __half* h1B    = p_h1    + (size_t)b * NN_NODE * FDIM;
        __half* xhB    = p_xh    + (size_t)b * NN_NODE * FDIM;
        __half* wtB    = p_wt    + (size_t)b * NLAYERS * FDIM * FDIM;

        k_halfcpy<<<(NN_NODE * FDIM / 4 + 255) / 256, 256, 0, st>>>(x0, xhB, NN_NODE * FDIM / 4);
        k_halfT<<<(NLAYERS * FDIM * FDIM + 255) / 256, 256, 0, st>>>(W, wtB, NLAYERS * FDIM * FDIM);

        k_deg_cnt<<<E_NUM / 256, 256, 0, st>>>(edges, w, b);
        k_scan<<<1, 1024, 0, st>>>(b);
        k_fill<<<E_NUM / 256, 256, 0, st>>>(edges, w, b);

        const __half* hin = xhB;
        int lda = FDIM;
        for (int i = 0; i < NLAYERS; i++) {
            k_gemm_f16<0, 1, 0><<<dim3(FDIM / 128, MT), 256, SM_F16, st>>>(
                NN_NODE, FDIM, FDIM, hin, lda, wtB + (size_t)i * FDIM * FDIM, FDIM,
                h1B, FDIM, nullptr);
            k_aggregate<<<NN_NODE, 64, 0, st>>>(h1B, b, bias + (size_t)i * FDIM, i);
            hin = featsB + (size_t)i * FDIM;
            lda = KTOT;
        }

        k_attfc<<<1, 32, 0, st>>>(fc1w, fc1b, fc2w, fc2b, b);
        k_weff<<<(OC * KTOT + 255) / 256, 256, 0, st>>>(cw, b);

        k_gemm_f16<1, 1, 0><<<dim3(1, MT), 256, SM_F16, st>>>(
            NN_NODE, OC, KTOT, featsB, KTOT,
            p_weff + (size_t)b * OC * KTOT, KTOT,
            p_emb + (size_t)b * NN_NODE * OC, OC, cb);
    }

    cudaEventRecord(g_hx.ev_j0, g_hx.s0);
    cudaEventRecord(g_hx.ev_j1, g_hx.s1);
    cudaStreamWaitEvent(0, g_hx.ev_j0, 0);
    cudaStreamWaitEvent(0, g_hx.ev_j1, 0);

    k_gemm_f16<0, 0, 1><<<dim3(MT, MT), 256, SM_F16>>>(
        NN_NODE, NN_NODE, OC,
        p_emb, OC,
        p_emb + (size_t)NN_NODE * OC, OC,
        out, NN_NODE, nullptr);
}